// round 13
// baseline (speedup 1.0000x reference)
#include <cuda_runtime.h>

#define BATCH 64
#define T 128
#define N 32
#define M 8
#define P 16
#define MA 34     // padded row stride
#define NCH 16    // backward-scan chunks
#define CHS 8
#define NCHF 16   // forward-scan chunks
#define CHSF 8
#define NMA (N * MA)

// ---------------- global scratch (backward, unchanged layouts) ----------
__device__ float g_muf[BATCH * T * N];
__device__ float g_mup[BATCH * T * N];
__device__ float g_Sigf[(size_t)BATCH * T * N * N];
__device__ float g_Sigp[(size_t)BATCH * T * N * N];
__device__ float g_J[(size_t)BATCH * (T - 1) * N * N];
__device__ float g_M[(size_t)BATCH * (T - 1) * N * N];
__device__ float g_c[(size_t)BATCH * (T - 1) * N];
__device__ float g_OX[(size_t)BATCH * NCH * N * N];
__device__ float g_OM[(size_t)BATCH * NCH * N * N];
__device__ float g_Oc[(size_t)BATCH * NCH * N];
__device__ float g_eS[(size_t)BATCH * NCH * N * N];
__device__ float g_emu[(size_t)BATCH * NCH * N];
// ---------------- forward-scan scratch ----------------------------------
__device__ float g_eA[(size_t)BATCH * T * N * N];
__device__ float g_eC[(size_t)BATCH * T * N * N];
__device__ float g_eJ[(size_t)BATCH * T * N * N];
__device__ float g_eb[BATCH * T * N];
__device__ float g_eh[BATCH * T * N];
__device__ float g_fA[(size_t)BATCH * NCHF * N * N];
__device__ float g_fC[(size_t)BATCH * NCHF * N * N];
__device__ float g_fJ[(size_t)BATCH * NCHF * N * N];
__device__ float g_fb[BATCH * NCHF * N];
__device__ float g_fh[BATCH * NCHF * N];
__device__ float g_enSig[(size_t)BATCH * NCHF * N * N];
__device__ float g_enMu[BATCH * NCHF * N];

// =====================================================================
// kE: per-(b,t) filter element. grid (T, BATCH), 128 thr.
// Element: eA = A - q W^T V ; eC = qI - q^2 W^T C ; eJ = V^T L ;
//          eb = Bu + q W^T w ; eh = L^T w
// with V=CA, S=q CC^T + rI, [W|L]=S^{-1}[C|V], w=y-C*Bu, q=r=0.01.
// =====================================================================
__global__ __launch_bounds__(128) void kE(
    const float* __restrict__ Y, const float* __restrict__ U,
    const float* __restrict__ A, const float* __restrict__ Bm,
    const float* __restrict__ C)
{
    const int t = blockIdx.x, b = blockIdx.y;
    const size_t bt = (size_t)b * T + t;
    const int tid = threadIdx.x;

    __shared__ __align__(16) float sA[NMA];
    __shared__ __align__(16) float sC[P * MA], sV[P * MA], sW[P * MA], sL[P * MA];
    __shared__ __align__(16) float sS[P * 18], sB[N * M];
    __shared__ float sBu[N], sw[P], sy[P], su[M];

    {
        const float2* Ag = (const float2*)(A + bt * (N * N));
        const float2* Cg = (const float2*)(C + bt * (P * N));
        const float2* Bg = (const float2*)(Bm + bt * (N * M));
        for (int i2 = tid; i2 < 512; i2 += 128) {
            int r = i2 >> 4, c = (i2 & 15) * 2;
            *(float2*)(sA + r * MA + c) = Ag[i2];
        }
        for (int i2 = tid; i2 < 256; i2 += 128) {
            int r = i2 >> 4, c = (i2 & 15) * 2;
            *(float2*)(sC + r * MA + c) = Cg[i2];
        }
        if (tid < 128) ((float2*)sB)[tid] = Bg[tid];
        if (tid < P) sy[tid] = Y[bt * P + tid];
        if (tid < M) su[tid] = U[bt * M + tid];
    }
    __syncthreads();

    // R0: V = C*A (128 2x2 tiles) ; tid<32: Bu
    {
        const int r0 = (tid >> 4) * 2, c0 = (tid & 15) * 2;
        const float2* Cr0 = (const float2*)(sC + r0 * MA);
        const float2* Cr1 = (const float2*)(sC + (r0 + 1) * MA);
        float a00 = 0, a01 = 0, a10 = 0, a11 = 0;
        #pragma unroll
        for (int k2 = 0; k2 < 16; k2++) {
            float2 x0 = Cr0[k2], x1 = Cr1[k2];
            float2 y0 = *(const float2*)(sA + (2 * k2) * MA + c0);
            float2 y1 = *(const float2*)(sA + (2 * k2 + 1) * MA + c0);
            a00 += x0.x * y0.x + x0.y * y1.x;  a01 += x0.x * y0.y + x0.y * y1.y;
            a10 += x1.x * y0.x + x1.y * y1.x;  a11 += x1.x * y0.y + x1.y * y1.y;
        }
        *(float2*)(sV + r0 * MA + c0) = make_float2(a00, a01);
        *(float2*)(sV + (r0 + 1) * MA + c0) = make_float2(a10, a11);
        if (tid < N) {
            float s = 0.f;
            #pragma unroll
            for (int j = 0; j < M; j++) s += sB[tid * M + j] * su[j];
            sBu[tid] = s;
        }
    }
    __syncthreads();

    // R1: S = 0.01*C C^T + 0.01 I (tid<64) ; w = y - C*Bu (tid 64..79)
    if (tid < 64) {
        const int i0 = (tid >> 3) * 2, j0 = (tid & 7) * 2;
        const float2* Ci0 = (const float2*)(sC + i0 * MA);
        const float2* Ci1 = (const float2*)(sC + (i0 + 1) * MA);
        const float2* Cj0 = (const float2*)(sC + j0 * MA);
        const float2* Cj1 = (const float2*)(sC + (j0 + 1) * MA);
        float a00 = 0, a01 = 0, a10 = 0, a11 = 0;
        #pragma unroll
        for (int k2 = 0; k2 < 16; k2++) {
            float2 x0 = Ci0[k2], x1 = Ci1[k2], y0 = Cj0[k2], y1 = Cj1[k2];
            a00 += x0.x * y0.x + x0.y * y0.y;  a01 += x0.x * y1.x + x0.y * y1.y;
            a10 += x1.x * y0.x + x1.y * y0.y;  a11 += x1.x * y1.x + x1.y * y1.y;
        }
        a00 = 0.01f * a00 + ((i0 == j0) ? 0.01f : 0.f);
        a11 = 0.01f * a11 + ((i0 == j0) ? 0.01f : 0.f);
        a01 *= 0.01f; a10 *= 0.01f;
        *(float2*)(sS + i0 * 18 + j0) = make_float2(a00, a01);
        *(float2*)(sS + (i0 + 1) * 18 + j0) = make_float2(a10, a11);
    } else if (tid < 80) {
        const int i = tid - 64;
        const float2* Cr = (const float2*)(sC + i * MA);
        float s = sy[i];
        #pragma unroll
        for (int j = 0; j < 16; j++) {
            float2 cv = Cr[j];
            s -= cv.x * sBu[2 * j] + cv.y * sBu[2 * j + 1];
        }
        sw[i] = s;
    }
    __syncthreads();

    // R2: warp0 GJ: S [W|L] = [C|V]
    if (tid < 32) {
        const int c = tid;
        float Sc[P], R1c[P], R2c[P];
        #pragma unroll
        for (int rr = 0; rr < P; rr++) {
            Sc[rr] = sS[rr * 18 + (c & 15)];
            R1c[rr] = sC[rr * MA + c];
            R2c[rr] = sV[rr * MA + c];
        }
        #pragma unroll
        for (int j = 0; j < P; j++) {
            float fj = __shfl_sync(0xffffffffu, Sc[j], j);
            float pinv = 1.0f / fj;
            Sc[j] *= pinv; R1c[j] *= pinv; R2c[j] *= pinv;
            float scj = Sc[j], r1j = R1c[j], r2j = R2c[j];
            #pragma unroll
            for (int rr = 0; rr < P; rr++) {
                if (rr != j) {
                    float f = __shfl_sync(0xffffffffu, Sc[rr], j);
                    Sc[rr] -= f * scj; R1c[rr] -= f * r1j; R2c[rr] -= f * r2j;
                }
            }
        }
        #pragma unroll
        for (int rr = 0; rr < P; rr++) {
            sW[rr * MA + c] = R1c[rr];
            sL[rr * MA + c] = R2c[rr];
        }
    }
    __syncthreads();

    // R3: outputs (plain products; W^T C and V^T L are symmetric exactly)
    const size_t mb = bt * (N * N);
    #pragma unroll
    for (int s = 0; s < 2; s++) {
        const int id = tid + s * 128;
        const int r0 = (id >> 4) * 2, c0 = (id & 15) * 2;
        float a00 = 0, a01 = 0, a10 = 0, a11 = 0;   // W^T V
        float c00 = 0, c01 = 0, c10 = 0, c11 = 0;   // W^T C
        float j00 = 0, j01 = 0, j10 = 0, j11 = 0;   // V^T L
        #pragma unroll
        for (int j = 0; j < P; j++) {
            float wr0 = sW[j * MA + r0], wr1 = sW[j * MA + r0 + 1];
            float vr0 = sV[j * MA + r0], vr1 = sV[j * MA + r0 + 1];
            float2 vc = *(const float2*)(sV + j * MA + c0);
            float2 cc = *(const float2*)(sC + j * MA + c0);
            float2 lc = *(const float2*)(sL + j * MA + c0);
            a00 += wr0 * vc.x;  a01 += wr0 * vc.y;
            a10 += wr1 * vc.x;  a11 += wr1 * vc.y;
            c00 += wr0 * cc.x;  c01 += wr0 * cc.y;
            c10 += wr1 * cc.x;  c11 += wr1 * cc.y;
            j00 += vr0 * lc.x;  j01 += vr0 * lc.y;
            j10 += vr1 * lc.x;  j11 += vr1 * lc.y;
        }
        float2 Ar0 = *(const float2*)(sA + r0 * MA + c0);
        float2 Ar1 = *(const float2*)(sA + (r0 + 1) * MA + c0);
        *(float2*)(g_eA + mb + r0 * 32 + c0) =
            make_float2(Ar0.x - 0.01f * a00, Ar0.y - 0.01f * a01);
        *(float2*)(g_eA + mb + (r0 + 1) * 32 + c0) =
            make_float2(Ar1.x - 0.01f * a10, Ar1.y - 0.01f * a11);
        float d00 = (r0 == c0) ? 0.01f : 0.f;
        float d01 = (r0 == c0 + 1) ? 0.01f : 0.f;
        float d10 = (r0 + 1 == c0) ? 0.01f : 0.f;
        float d11 = (r0 == c0) ? 0.01f : 0.f;
        *(float2*)(g_eC + mb + r0 * 32 + c0) =
            make_float2(d00 - 1e-4f * c00, d01 - 1e-4f * c01);
        *(float2*)(g_eC + mb + (r0 + 1) * 32 + c0) =
            make_float2(d10 - 1e-4f * c10, d11 - 1e-4f * c11);
        *(float2*)(g_eJ + mb + r0 * 32 + c0) = make_float2(j00, j01);
        *(float2*)(g_eJ + mb + (r0 + 1) * 32 + c0) = make_float2(j10, j11);
    }
    if (tid < N) {
        float bb = sBu[tid], hh = 0.f;
        #pragma unroll
        for (int j = 0; j < P; j++) {
            bb += 0.01f * sW[j * MA + tid] * sw[j];
            hh += sL[j * MA + tid] * sw[j];
        }
        g_eb[bt * N + tid] = bb;
        g_eh[bt * N + tid] = hh;
    }
}

// =====================================================================
// kFA: compose chunk elements. grid (NCHF, BATCH), 256 thr, dynamic smem.
// =====================================================================
#define FA_OA  0
#define FA_OC  (FA_OA + 2 * NMA)
#define FA_OJ  (FA_OC + 2 * NMA)
#define FA_EA  (FA_OJ + 2 * NMA)
#define FA_EC  (FA_EA + NMA)
#define FA_EJ  (FA_EC + NMA)
#define FA_T0  (FA_EJ + NMA)
#define FA_T1  (FA_T0 + NMA)
#define FA_T2  (FA_T1 + NMA)
#define FA_T3  (FA_T2 + NMA)
#define FA_T4  (FA_T3 + NMA)
#define FA_OB  (FA_T4 + NMA)
#define FA_OH  (FA_OB + 2 * N)
#define FA_EB  (FA_OH + 2 * N)
#define FA_EH  (FA_EB + N)
#define FA_V1  (FA_EH + N)
#define FA_V2  (FA_V1 + N)
#define FA_V3  (FA_V2 + N)
#define FA_V4  (FA_V3 + N)
#define FA_TOT (FA_V4 + N)
#define FA_BYTES (FA_TOT * 4)

extern __shared__ float fdsm[];

__global__ __launch_bounds__(256) void kFA()
{
    const int k = blockIdx.x, b = blockIdx.y;
    const int t_lo = CHSF * k;
    const int tid = threadIdx.x;
    const int r0 = (tid >> 4) * 2, c0 = (tid & 15) * 2;

    float* EA = fdsm + FA_EA;  float* EC = fdsm + FA_EC;  float* EJ = fdsm + FA_EJ;
    float* T0 = fdsm + FA_T0;  float* T1 = fdsm + FA_T1;  float* T2 = fdsm + FA_T2;
    float* T3 = fdsm + FA_T3;  float* T4 = fdsm + FA_T4;
    float* Eb = fdsm + FA_EB;  float* Eh = fdsm + FA_EH;
    float* vt1 = fdsm + FA_V1; float* vw2 = fdsm + FA_V2;
    float* vv1 = fdsm + FA_V3; float* vu2 = fdsm + FA_V4;

    int cur = 0;
    {
        const size_t mb = ((size_t)b * T + t_lo) * (N * N);
        const size_t vb = ((size_t)b * T + t_lo) * N;
        float* OA = fdsm + FA_OA;
        float* OC = fdsm + FA_OC;
        float* OJ = fdsm + FA_OJ;
        for (int i2 = tid; i2 < 512; i2 += 256) {
            int r = i2 >> 4, c = (i2 & 15) * 2;
            *(float2*)(OA + r * MA + c) = *(const float2*)(g_eA + mb + i2 * 2);
            *(float2*)(OC + r * MA + c) = *(const float2*)(g_eC + mb + i2 * 2);
            *(float2*)(OJ + r * MA + c) = *(const float2*)(g_eJ + mb + i2 * 2);
        }
        if (tid < N) {
            (fdsm + FA_OB)[tid] = g_eb[vb + tid];
            (fdsm + FA_OH)[tid] = g_eh[vb + tid];
        }
    }
    __syncthreads();

    for (int t = t_lo + 1; t <= t_lo + CHSF - 1; t++) {
        const int nxt = cur ^ 1;
        float* OA = fdsm + FA_OA + cur * NMA;
        float* OC = fdsm + FA_OC + cur * NMA;
        float* OJ = fdsm + FA_OJ + cur * NMA;
        float* Ob = fdsm + FA_OB + cur * N;
        float* Oh = fdsm + FA_OH + cur * N;
        float* nOA = fdsm + FA_OA + nxt * NMA;
        float* nOC = fdsm + FA_OC + nxt * NMA;
        float* nOJ = fdsm + FA_OJ + nxt * NMA;
        float* nOb = fdsm + FA_OB + nxt * N;
        float* nOh = fdsm + FA_OH + nxt * N;

        {
            const size_t mb = ((size_t)b * T + t) * (N * N);
            const size_t vb = ((size_t)b * T + t) * N;
            for (int i2 = tid; i2 < 512; i2 += 256) {
                int r = i2 >> 4, c = (i2 & 15) * 2;
                *(float2*)(EA + r * MA + c) = *(const float2*)(g_eA + mb + i2 * 2);
                *(float2*)(EC + r * MA + c) = *(const float2*)(g_eC + mb + i2 * 2);
                *(float2*)(EJ + r * MA + c) = *(const float2*)(g_eJ + mb + i2 * 2);
            }
            if (tid < N) { Eb[tid] = g_eb[vb + tid]; Eh[tid] = g_eh[vb + tid]; }
        }
        __syncthreads();

        // R0: T0 = I + OC*EJ
        {
            const float2* Xr0 = (const float2*)(OC + r0 * MA);
            const float2* Xr1 = (const float2*)(OC + (r0 + 1) * MA);
            float a00 = (r0 == c0) ? 1.f : 0.f, a01 = 0, a10 = 0;
            float a11 = (r0 == c0) ? 1.f : 0.f;
            #pragma unroll
            for (int k2 = 0; k2 < 16; k2++) {
                float2 x0 = Xr0[k2], x1 = Xr1[k2];
                float2 y0 = *(const float2*)(EJ + (2 * k2) * MA + c0);
                float2 y1 = *(const float2*)(EJ + (2 * k2 + 1) * MA + c0);
                a00 += x0.x * y0.x + x0.y * y1.x;  a01 += x0.x * y0.y + x0.y * y1.y;
                a10 += x1.x * y0.x + x1.y * y1.x;  a11 += x1.x * y0.y + x1.y * y1.y;
            }
            *(float2*)(T0 + r0 * MA + c0) = make_float2(a00, a01);
            *(float2*)(T0 + (r0 + 1) * MA + c0) = make_float2(a10, a11);
        }
        __syncthreads();

        // R1: warp0 GJ invert T0 -> T1 ; vt1 = Ob + OC*Eh ; vw2 = Eh - EJ*Ob
        if (tid < 32) {
            const int c = tid;
            float Mc[N], Ic[N];
            #pragma unroll
            for (int rr = 0; rr < N; rr++) {
                Mc[rr] = T0[rr * MA + c];
                Ic[rr] = (rr == c) ? 1.f : 0.f;
            }
            #pragma unroll
            for (int j = 0; j < N; j++) {
                float fj = __shfl_sync(0xffffffffu, Mc[j], j);
                float pinv = 1.0f / fj;
                Mc[j] *= pinv; Ic[j] *= pinv;
                float mj = Mc[j], ij = Ic[j];
                #pragma unroll
                for (int rr = 0; rr < N; rr++) {
                    if (rr != j) {
                        float f = __shfl_sync(0xffffffffu, Mc[rr], j);
                        Mc[rr] -= f * mj; Ic[rr] -= f * ij;
                    }
                }
            }
            #pragma unroll
            for (int rr = 0; rr < N; rr++) T1[rr * MA + c] = Ic[rr];
        } else if (tid < 64) {
            const int i = tid - 32;
            const float2* Rr = (const float2*)(OC + i * MA);
            float s = Ob[i];
            #pragma unroll
            for (int j = 0; j < 16; j++) {
                float2 x = Rr[j];
                s += x.x * Eh[2 * j] + x.y * Eh[2 * j + 1];
            }
            vt1[i] = s;
        } else if (tid < 96) {
            const int i = tid - 64;
            const float2* Rr = (const float2*)(EJ + i * MA);
            float s = Eh[i];
            #pragma unroll
            for (int j = 0; j < 16; j++) {
                float2 x = Rr[j];
                s -= x.x * Ob[2 * j] + x.y * Ob[2 * j + 1];
            }
            vw2[i] = s;
        }
        __syncthreads();

        // R2: T2 = T1*OA ; T3 = T1*OC ; vv1 = T1*vt1 ; vu2 = T1^T*vw2
        {
            const float2* Xr0 = (const float2*)(T1 + r0 * MA);
            const float2* Xr1 = (const float2*)(T1 + (r0 + 1) * MA);
            float a00 = 0, a01 = 0, a10 = 0, a11 = 0;
            float b00 = 0, b01 = 0, b10 = 0, b11 = 0;
            #pragma unroll
            for (int k2 = 0; k2 < 16; k2++) {
                float2 x0 = Xr0[k2], x1 = Xr1[k2];
                float2 ya0 = *(const float2*)(OA + (2 * k2) * MA + c0);
                float2 ya1 = *(const float2*)(OA + (2 * k2 + 1) * MA + c0);
                float2 yc0 = *(const float2*)(OC + (2 * k2) * MA + c0);
                float2 yc1 = *(const float2*)(OC + (2 * k2 + 1) * MA + c0);
                a00 += x0.x * ya0.x + x0.y * ya1.x;  a01 += x0.x * ya0.y + x0.y * ya1.y;
                a10 += x1.x * ya0.x + x1.y * ya1.x;  a11 += x1.x * ya0.y + x1.y * ya1.y;
                b00 += x0.x * yc0.x + x0.y * yc1.x;  b01 += x0.x * yc0.y + x0.y * yc1.y;
                b10 += x1.x * yc0.x + x1.y * yc1.x;  b11 += x1.x * yc0.y + x1.y * yc1.y;
            }
            *(float2*)(T2 + r0 * MA + c0) = make_float2(a00, a01);
            *(float2*)(T2 + (r0 + 1) * MA + c0) = make_float2(a10, a11);
            *(float2*)(T3 + r0 * MA + c0) = make_float2(b00, b01);
            *(float2*)(T3 + (r0 + 1) * MA + c0) = make_float2(b10, b11);
        }
        if (tid < 32) {
            const float2* Rr = (const float2*)(T1 + tid * MA);
            float s = 0.f;
            #pragma unroll
            for (int j = 0; j < 16; j++) {
                float2 x = Rr[j];
                s += x.x * vt1[2 * j] + x.y * vt1[2 * j + 1];
            }
            vv1[tid] = s;
        }
        __syncthreads();
        if (tid < 32) {
            float s = 0.f;
            #pragma unroll
            for (int kk = 0; kk < N; kk++) s += T1[kk * MA + tid] * vw2[kk];
            vu2[tid] = s;
        }

        // R3: nOA = EA*T2 ; T0 = EJ*OA ; nOb = EA*vv1 + Eb
        {
            const float2* Er0 = (const float2*)(EA + r0 * MA);
            const float2* Er1 = (const float2*)(EA + (r0 + 1) * MA);
            const float2* Jr0 = (const float2*)(EJ + r0 * MA);
            const float2* Jr1 = (const float2*)(EJ + (r0 + 1) * MA);
            float a00 = 0, a01 = 0, a10 = 0, a11 = 0;
            float p00 = 0, p01 = 0, p10 = 0, p11 = 0;
            #pragma unroll
            for (int k2 = 0; k2 < 16; k2++) {
                float2 x0 = Er0[k2], x1 = Er1[k2];
                float2 y0 = *(const float2*)(T2 + (2 * k2) * MA + c0);
                float2 y1 = *(const float2*)(T2 + (2 * k2 + 1) * MA + c0);
                float2 z0 = Jr0[k2], z1 = Jr1[k2];
                float2 w0 = *(const float2*)(OA + (2 * k2) * MA + c0);
                float2 w1 = *(const float2*)(OA + (2 * k2 + 1) * MA + c0);
                a00 += x0.x * y0.x + x0.y * y1.x;  a01 += x0.x * y0.y + x0.y * y1.y;
                a10 += x1.x * y0.x + x1.y * y1.x;  a11 += x1.x * y0.y + x1.y * y1.y;
                p00 += z0.x * w0.x + z0.y * w1.x;  p01 += z0.x * w0.y + z0.y * w1.y;
                p10 += z1.x * w0.x + z1.y * w1.x;  p11 += z1.x * w0.y + z1.y * w1.y;
            }
            *(float2*)(nOA + r0 * MA + c0) = make_float2(a00, a01);
            *(float2*)(nOA + (r0 + 1) * MA + c0) = make_float2(a10, a11);
            *(float2*)(T0 + r0 * MA + c0) = make_float2(p00, p01);
            *(float2*)(T0 + (r0 + 1) * MA + c0) = make_float2(p10, p11);
        }
        if (tid < 32) {
            const float2* Er = (const float2*)(EA + tid * MA);
            float s = Eb[tid];
            #pragma unroll
            for (int j = 0; j < 16; j++) {
                float2 x = Er[j];
                s += x.x * vv1[2 * j] + x.y * vv1[2 * j + 1];
            }
            nOb[tid] = s;
        }
        __syncthreads();

        // R4: T2' = EA*T3 ; T4 = T1^T*T0
        {
            const float2* Er0 = (const float2*)(EA + r0 * MA);
            const float2* Er1 = (const float2*)(EA + (r0 + 1) * MA);
            float a00 = 0, a01 = 0, a10 = 0, a11 = 0;
            #pragma unroll
            for (int k2 = 0; k2 < 16; k2++) {
                float2 x0 = Er0[k2], x1 = Er1[k2];
                float2 y0 = *(const float2*)(T3 + (2 * k2) * MA + c0);
                float2 y1 = *(const float2*)(T3 + (2 * k2 + 1) * MA + c0);
                a00 += x0.x * y0.x + x0.y * y1.x;  a01 += x0.x * y0.y + x0.y * y1.y;
                a10 += x1.x * y0.x + x1.y * y1.x;  a11 += x1.x * y0.y + x1.y * y1.y;
            }
            float q00 = 0, q01 = 0, q10 = 0, q11 = 0;
            #pragma unroll
            for (int kk = 0; kk < N; kk++) {
                float x0 = T1[kk * MA + r0], x1 = T1[kk * MA + r0 + 1];
                float2 y = *(const float2*)(T0 + kk * MA + c0);
                q00 += x0 * y.x;  q01 += x0 * y.y;
                q10 += x1 * y.x;  q11 += x1 * y.y;
            }
            __syncthreads();
            *(float2*)(T2 + r0 * MA + c0) = make_float2(a00, a01);
            *(float2*)(T2 + (r0 + 1) * MA + c0) = make_float2(a10, a11);
            *(float2*)(T4 + r0 * MA + c0) = make_float2(q00, q01);
            *(float2*)(T4 + (r0 + 1) * MA + c0) = make_float2(q10, q11);
        }
        __syncthreads();

        // R5: nOC = T2*EA^T + EC ; nOJ = OA^T*T4 + OJ ; nOh
        {
            const float2* Hr0 = (const float2*)(T2 + r0 * MA);
            const float2* Hr1 = (const float2*)(T2 + (r0 + 1) * MA);
            const float2* Ac0 = (const float2*)(EA + c0 * MA);
            const float2* Ac1 = (const float2*)(EA + (c0 + 1) * MA);
            float a00 = 0, a01 = 0, a10 = 0, a11 = 0;
            #pragma unroll
            for (int k2 = 0; k2 < 16; k2++) {
                float2 x0 = Hr0[k2], x1 = Hr1[k2], y0 = Ac0[k2], y1 = Ac1[k2];
                a00 += x0.x * y0.x + x0.y * y0.y;  a01 += x0.x * y1.x + x0.y * y1.y;
                a10 += x1.x * y0.x + x1.y * y0.y;  a11 += x1.x * y1.x + x1.y * y1.y;
            }
            float2 e0 = *(const float2*)(EC + r0 * MA + c0);
            float2 e1 = *(const float2*)(EC + (r0 + 1) * MA + c0);
            *(float2*)(nOC + r0 * MA + c0) = make_float2(e0.x + a00, e0.y + a01);
            *(float2*)(nOC + (r0 + 1) * MA + c0) = make_float2(e1.x + a10, e1.y + a11);

            float j00 = 0, j01 = 0, j10 = 0, j11 = 0;
            #pragma unroll
            for (int kk = 0; kk < N; kk++) {
                float x0 = OA[kk * MA + r0], x1 = OA[kk * MA + r0 + 1];
                float2 y = *(const float2*)(T4 + kk * MA + c0);
                j00 += x0 * y.x;  j01 += x0 * y.y;
                j10 += x1 * y.x;  j11 += x1 * y.y;
            }
            float2 o0 = *(const float2*)(OJ + r0 * MA + c0);
            float2 o1 = *(const float2*)(OJ + (r0 + 1) * MA + c0);
            *(float2*)(nOJ + r0 * MA + c0) = make_float2(o0.x + j00, o0.y + j01);
            *(float2*)(nOJ + (r0 + 1) * MA + c0) = make_float2(o1.x + j10, o1.y + j11);
        }
        if (tid < 32) {
            float s = Oh[tid];
            #pragma unroll
            for (int kk = 0; kk < N; kk++) s += OA[kk * MA + tid] * vu2[kk];
            nOh[tid] = s;
        }
        __syncthreads();
        cur = nxt;
    }

    {
        float* OA = fdsm + FA_OA + cur * NMA;
        float* OC = fdsm + FA_OC + cur * NMA;
        float* OJ = fdsm + FA_OJ + cur * NMA;
        const size_t fb = ((size_t)b * NCHF + k) * (N * N);
        const size_t fv = ((size_t)b * NCHF + k) * N;
        for (int i2 = tid; i2 < 512; i2 += 256) {
            int r = i2 >> 4, c = (i2 & 15) * 2;
            *(float2*)(g_fA + fb + i2 * 2) = *(const float2*)(OA + r * MA + c);
            *(float2*)(g_fC + fb + i2 * 2) = *(const float2*)(OC + r * MA + c);
            *(float2*)(g_fJ + fb + i2 * 2) = *(const float2*)(OJ + r * MA + c);
        }
        if (tid < N) {
            g_fb[fv + tid] = (fdsm + FA_OB + cur * N)[tid];
            g_fh[fv + tid] = (fdsm + FA_OH + cur * N)[tid];
        }
    }
}

// =====================================================================
// kFB: prefix over chunk ops -> entry states. grid BATCH, 256 thr.
// =====================================================================
__global__ __launch_bounds__(256) void kFB(
    const float* __restrict__ mu0, const float* __restrict__ Sig0)
{
    const int b = blockIdx.x;
    const int tid = threadIdx.x;
    const int r0 = (tid >> 4) * 2, c0 = (tid & 15) * 2;

    __shared__ __align__(16) float sSig[NMA], sfA[NMA], sfC[NMA], sfJ[NMA];
    __shared__ __align__(16) float sT0[NMA], sT1[NMA], sT2[NMA];
    __shared__ float sMu[N], sfb[N], sfh[N], vt1[N], vv1[N], vnm[N];

    {
        float2* ge = (float2*)(g_enSig + ((size_t)b * NCHF) * (N * N));
        for (int i2 = tid; i2 < 512; i2 += 256) {
            int r = i2 >> 4, c = (i2 & 15) * 2;
            float2 v = ((const float2*)Sig0)[i2];
            *(float2*)(sSig + r * MA + c) = v;
            ge[i2] = v;
        }
        if (tid < N) {
            sMu[tid] = mu0[tid];
            g_enMu[(size_t)b * NCHF * N + tid] = mu0[tid];
        }
    }
    __syncthreads();

    for (int k = 0; k < NCHF - 1; k++) {
        {
            const size_t fb = ((size_t)b * NCHF + k) * (N * N);
            const size_t fv = ((size_t)b * NCHF + k) * N;
            for (int i2 = tid; i2 < 512; i2 += 256) {
                int r = i2 >> 4, c = (i2 & 15) * 2;
                *(float2*)(sfA + r * MA + c) = *(const float2*)(g_fA + fb + i2 * 2);
                *(float2*)(sfC + r * MA + c) = *(const float2*)(g_fC + fb + i2 * 2);
                *(float2*)(sfJ + r * MA + c) = *(const float2*)(g_fJ + fb + i2 * 2);
            }
            if (tid < N) { sfb[tid] = g_fb[fv + tid]; sfh[tid] = g_fh[fv + tid]; }
        }
        __syncthreads();

        // R0: T0 = I + Sig*fJ
        {
            const float2* Xr0 = (const float2*)(sSig + r0 * MA);
            const float2* Xr1 = (const float2*)(sSig + (r0 + 1) * MA);
            float a00 = (r0 == c0) ? 1.f : 0.f, a01 = 0, a10 = 0;
            float a11 = (r0 == c0) ? 1.f : 0.f;
            #pragma unroll
            for (int k2 = 0; k2 < 16; k2++) {
                float2 x0 = Xr0[k2], x1 = Xr1[k2];
                float2 y0 = *(const float2*)(sfJ + (2 * k2) * MA + c0);
                float2 y1 = *(const float2*)(sfJ + (2 * k2 + 1) * MA + c0);
                a00 += x0.x * y0.x + x0.y * y1.x;  a01 += x0.x * y0.y + x0.y * y1.y;
                a10 += x1.x * y0.x + x1.y * y1.x;  a11 += x1.x * y0.y + x1.y * y1.y;
            }
            *(float2*)(sT0 + r0 * MA + c0) = make_float2(a00, a01);
            *(float2*)(sT0 + (r0 + 1) * MA + c0) = make_float2(a10, a11);
        }
        __syncthreads();

        // R1: warp0 GJ invert T0 -> T1 ; vt1 = Mu + Sig*fh
        if (tid < 32) {
            const int c = tid;
            float Mc[N], Ic[N];
            #pragma unroll
            for (int rr = 0; rr < N; rr++) {
                Mc[rr] = sT0[rr * MA + c];
                Ic[rr] = (rr == c) ? 1.f : 0.f;
            }
            #pragma unroll
            for (int j = 0; j < N; j++) {
                float fj = __shfl_sync(0xffffffffu, Mc[j], j);
                float pinv = 1.0f / fj;
                Mc[j] *= pinv; Ic[j] *= pinv;
                float mj = Mc[j], ij = Ic[j];
                #pragma unroll
                for (int rr = 0; rr < N; rr++) {
                    if (rr != j) {
                        float f = __shfl_sync(0xffffffffu, Mc[rr], j);
                        Mc[rr] -= f * mj; Ic[rr] -= f * ij;
                    }
                }
            }
            #pragma unroll
            for (int rr = 0; rr < N; rr++) sT1[rr * MA + c] = Ic[rr];
        } else if (tid < 64) {
            const int i = tid - 32;
            const float2* Rr = (const float2*)(sSig + i * MA);
            float s = sMu[i];
            #pragma unroll
            for (int j = 0; j < 16; j++) {
                float2 x = Rr[j];
                s += x.x * sfh[2 * j] + x.y * sfh[2 * j + 1];
            }
            vt1[i] = s;
        }
        __syncthreads();

        // R2: T2 = T1*Sig ; vv1 = T1*vt1
        {
            const float2* Xr0 = (const float2*)(sT1 + r0 * MA);
            const float2* Xr1 = (const float2*)(sT1 + (r0 + 1) * MA);
            float a00 = 0, a01 = 0, a10 = 0, a11 = 0;
            #pragma unroll
            for (int k2 = 0; k2 < 16; k2++) {
                float2 x0 = Xr0[k2], x1 = Xr1[k2];
                float2 y0 = *(const float2*)(sSig + (2 * k2) * MA + c0);
                float2 y1 = *(const float2*)(sSig + (2 * k2 + 1) * MA + c0);
                a00 += x0.x * y0.x + x0.y * y1.x;  a01 += x0.x * y0.y + x0.y * y1.y;
                a10 += x1.x * y0.x + x1.y * y1.x;  a11 += x1.x * y0.y + x1.y * y1.y;
            }
            *(float2*)(sT2 + r0 * MA + c0) = make_float2(a00, a01);
            *(float2*)(sT2 + (r0 + 1) * MA + c0) = make_float2(a10, a11);
        }
        if (tid < 32) {
            const float2* Rr = (const float2*)(sT1 + tid * MA);
            float s = 0.f;
            #pragma unroll
            for (int j = 0; j < 16; j++) {
                float2 x = Rr[j];
                s += x.x * vt1[2 * j] + x.y * vt1[2 * j + 1];
            }
            vv1[tid] = s;
        }
        __syncthreads();

        // R3: T0 = fA*T2 ; vnm = fA*vv1 + fb
        {
            const float2* Xr0 = (const float2*)(sfA + r0 * MA);
            const float2* Xr1 = (const float2*)(sfA + (r0 + 1) * MA);
            float a00 = 0, a01 = 0, a10 = 0, a11 = 0;
            #pragma unroll
            for (int k2 = 0; k2 < 16; k2++) {
                float2 x0 = Xr0[k2], x1 = Xr1[k2];
                float2 y0 = *(const float2*)(sT2 + (2 * k2) * MA + c0);
                float2 y1 = *(const float2*)(sT2 + (2 * k2 + 1) * MA + c0);
                a00 += x0.x * y0.x + x0.y * y1.x;  a01 += x0.x * y0.y + x0.y * y1.y;
                a10 += x1.x * y0.x + x1.y * y1.x;  a11 += x1.x * y0.y + x1.y * y1.y;
            }
            *(float2*)(sT0 + r0 * MA + c0) = make_float2(a00, a01);
            *(float2*)(sT0 + (r0 + 1) * MA + c0) = make_float2(a10, a11);
        }
        if (tid < 32) {
            const float2* Rr = (const float2*)(sfA + tid * MA);
            float s = sfb[tid];
            #pragma unroll
            for (int j = 0; j < 16; j++) {
                float2 x = Rr[j];
                s += x.x * vv1[2 * j] + x.y * vv1[2 * j + 1];
            }
            vnm[tid] = s;
        }
        __syncthreads();

        // R4: Sig = T0*fA^T + fC ; Mu = vnm ; store entry[k+1]
        {
            const float2* Hr0 = (const float2*)(sT0 + r0 * MA);
            const float2* Hr1 = (const float2*)(sT0 + (r0 + 1) * MA);
            const float2* Ac0 = (const float2*)(sfA + c0 * MA);
            const float2* Ac1 = (const float2*)(sfA + (c0 + 1) * MA);
            float a00 = 0, a01 = 0, a10 = 0, a11 = 0;
            #pragma unroll
            for (int k2 = 0; k2 < 16; k2++) {
                float2 x0 = Hr0[k2], x1 = Hr1[k2], y0 = Ac0[k2], y1 = Ac1[k2];
                a00 += x0.x * y0.x + x0.y * y0.y;  a01 += x0.x * y1.x + x0.y * y1.y;
                a10 += x1.x * y0.x + x1.y * y0.y;  a11 += x1.x * y1.x + x1.y * y1.y;
            }
            float2 c0v = *(const float2*)(sfC + r0 * MA + c0);
            float2 c1v = *(const float2*)(sfC + (r0 + 1) * MA + c0);
            float v00 = c0v.x + a00, v01 = c0v.y + a01;
            float v10 = c1v.x + a10, v11 = c1v.y + a11;
            *(float2*)(sSig + r0 * MA + c0) = make_float2(v00, v01);
            *(float2*)(sSig + (r0 + 1) * MA + c0) = make_float2(v10, v11);
            float* ge = g_enSig + ((size_t)b * NCHF + (k + 1)) * (N * N);
            *(float2*)(ge + r0 * 32 + c0) = make_float2(v00, v01);
            *(float2*)(ge + (r0 + 1) * 32 + c0) = make_float2(v10, v11);
        }
        if (tid < 32) {
            sMu[tid] = vnm[tid];
            g_enMu[((size_t)b * NCHF + (k + 1)) * N + tid] = vnm[tid];
        }
        __syncthreads();
    }
}

// =====================================================================
// kFC: sequential Kalman steps within chunk. grid (NCHF, BATCH), 256 thr.
// =====================================================================
__global__ __launch_bounds__(256) void kFC(
    const float* __restrict__ Y, const float* __restrict__ U,
    const float* __restrict__ A, const float* __restrict__ Bm,
    const float* __restrict__ C)
{
    const int k = blockIdx.x, b = blockIdx.y;
    const int t_lo = CHSF * k;
    const int tid = threadIdx.x;
    const int r0 = (tid >> 4) * 2, c0 = (tid & 15) * 2;

    __shared__ __align__(16) float sA[NMA], sSig[NMA], sAS[NMA], sSp[NMA];
    __shared__ __align__(16) float sC[P * MA], sCSp[P * MA], sX[P * MA];
    __shared__ __align__(16) float sS[P * 18], sB[N * M];
    __shared__ float smu[N], smup[N], sd[P], sy[P], su[M];

    {
        const float2* ge = (const float2*)(g_enSig + ((size_t)b * NCHF + k) * (N * N));
        for (int i2 = tid; i2 < 512; i2 += 256) {
            int r = i2 >> 4, c = (i2 & 15) * 2;
            *(float2*)(sSig + r * MA + c) = ge[i2];
        }
        if (tid < N) smu[tid] = g_enMu[((size_t)b * NCHF + k) * N + tid];
    }
    __syncthreads();

    for (int t = t_lo; t < t_lo + CHSF; t++) {
        const size_t bt = (size_t)b * T + t;
        {
            const float2* Ag = (const float2*)(A + bt * (N * N));
            const float2* Cg = (const float2*)(C + bt * (P * N));
            const float2* Bg = (const float2*)(Bm + bt * (N * M));
            for (int i2 = tid; i2 < 512; i2 += 256) {
                int r = i2 >> 4, c = (i2 & 15) * 2;
                *(float2*)(sA + r * MA + c) = Ag[i2];
            }
            if (tid < 256) {
                int r = tid >> 4, c = (tid & 15) * 2;
                *(float2*)(sC + r * MA + c) = Cg[tid];
            }
            if (tid < 128) ((float2*)sB)[tid] = Bg[tid];
            if (tid < P) sy[tid] = Y[bt * P + tid];
            else if (tid < P + M) su[tid - P] = U[bt * M + (tid - P)];
        }
        __syncthreads();

        // R0: AS = A*Sig ; mu_p
        {
            const float2* Xr0 = (const float2*)(sA + r0 * MA);
            const float2* Xr1 = (const float2*)(sA + (r0 + 1) * MA);
            float a00 = 0, a01 = 0, a10 = 0, a11 = 0;
            #pragma unroll
            for (int k2 = 0; k2 < 16; k2++) {
                float2 x0 = Xr0[k2], x1 = Xr1[k2];
                float2 y0 = *(const float2*)(sSig + (2 * k2) * MA + c0);
                float2 y1 = *(const float2*)(sSig + (2 * k2 + 1) * MA + c0);
                a00 += x0.x * y0.x + x0.y * y1.x;  a01 += x0.x * y0.y + x0.y * y1.y;
                a10 += x1.x * y0.x + x1.y * y1.x;  a11 += x1.x * y0.y + x1.y * y1.y;
            }
            *(float2*)(sAS + r0 * MA + c0) = make_float2(a00, a01);
            *(float2*)(sAS + (r0 + 1) * MA + c0) = make_float2(a10, a11);
        }
        if (tid < N) {
            const float2* Ar = (const float2*)(sA + tid * MA);
            float s = 0.f;
            #pragma unroll
            for (int j = 0; j < 16; j++) {
                float2 a = Ar[j];
                s += a.x * smu[2 * j] + a.y * smu[2 * j + 1];
            }
            const float2* Br = (const float2*)(sB + tid * M);
            #pragma unroll
            for (int j = 0; j < 4; j++) {
                float2 bb = Br[j];
                s += bb.x * su[2 * j] + bb.y * su[2 * j + 1];
            }
            smup[tid] = s;
            g_mup[bt * N + tid] = s;
        }
        __syncthreads();

        // R1: Sig_p = AS*A^T + qI ; write g_Sigp
        {
            const float2* Xr0 = (const float2*)(sAS + r0 * MA);
            const float2* Xr1 = (const float2*)(sAS + (r0 + 1) * MA);
            const float2* Yc0 = (const float2*)(sA + c0 * MA);
            const float2* Yc1 = (const float2*)(sA + (c0 + 1) * MA);
            float a00 = (r0 == c0) ? 0.01f : 0.f, a01 = 0, a10 = 0;
            float a11 = (r0 == c0) ? 0.01f : 0.f;
            #pragma unroll
            for (int k2 = 0; k2 < 16; k2++) {
                float2 x0 = Xr0[k2], x1 = Xr1[k2], y0 = Yc0[k2], y1 = Yc1[k2];
                a00 += x0.x * y0.x + x0.y * y0.y;  a01 += x0.x * y1.x + x0.y * y1.y;
                a10 += x1.x * y0.x + x1.y * y0.y;  a11 += x1.x * y1.x + x1.y * y1.y;
            }
            *(float2*)(sSp + r0 * MA + c0) = make_float2(a00, a01);
            *(float2*)(sSp + (r0 + 1) * MA + c0) = make_float2(a10, a11);
            float* gp = g_Sigp + (bt << 10);
            *(float2*)(gp + r0 * 32 + c0) = make_float2(a00, a01);
            *(float2*)(gp + (r0 + 1) * 32 + c0) = make_float2(a10, a11);
        }
        __syncthreads();

        // R2: CSp = C*Sig_p ; d
        if (tid < 128) {
            const int rr = (tid >> 4) * 2, cc = (tid & 15) * 2;
            const float2* Xr0 = (const float2*)(sC + rr * MA);
            const float2* Xr1 = (const float2*)(sC + (rr + 1) * MA);
            float a00 = 0, a01 = 0, a10 = 0, a11 = 0;
            #pragma unroll
            for (int k2 = 0; k2 < 16; k2++) {
                float2 x0 = Xr0[k2], x1 = Xr1[k2];
                float2 y0 = *(const float2*)(sSp + (2 * k2) * MA + cc);
                float2 y1 = *(const float2*)(sSp + (2 * k2 + 1) * MA + cc);
                a00 += x0.x * y0.x + x0.y * y1.x;  a01 += x0.x * y0.y + x0.y * y1.y;
                a10 += x1.x * y0.x + x1.y * y1.x;  a11 += x1.x * y0.y + x1.y * y1.y;
            }
            *(float2*)(sCSp + rr * MA + cc) = make_float2(a00, a01);
            *(float2*)(sCSp + (rr + 1) * MA + cc) = make_float2(a10, a11);
        } else if (tid < 144) {
            const int i = tid - 128;
            const float2* Cr = (const float2*)(sC + i * MA);
            float s = sy[i];
            #pragma unroll
            for (int j = 0; j < 16; j++) {
                float2 cv = Cr[j];
                s -= cv.x * smup[2 * j] + cv.y * smup[2 * j + 1];
            }
            sd[i] = s;
        }
        __syncthreads();

        // R3: S = CSp*C^T + rI
        if (tid < 64) {
            const int rr = (tid >> 3) * 2, cc = (tid & 7) * 2;
            const float2* Xr0 = (const float2*)(sCSp + rr * MA);
            const float2* Xr1 = (const float2*)(sCSp + (rr + 1) * MA);
            const float2* Yc0 = (const float2*)(sC + cc * MA);
            const float2* Yc1 = (const float2*)(sC + (cc + 1) * MA);
            float a00 = (rr == cc) ? 0.01f : 0.f, a01 = 0, a10 = 0;
            float a11 = (rr == cc) ? 0.01f : 0.f;
            #pragma unroll
            for (int k2 = 0; k2 < 16; k2++) {
                float2 x0 = Xr0[k2], x1 = Xr1[k2], y0 = Yc0[k2], y1 = Yc1[k2];
                a00 += x0.x * y0.x + x0.y * y0.y;  a01 += x0.x * y1.x + x0.y * y1.y;
                a10 += x1.x * y0.x + x1.y * y0.y;  a11 += x1.x * y1.x + x1.y * y1.y;
            }
            *(float2*)(sS + rr * 18 + cc) = make_float2(a00, a01);
            *(float2*)(sS + (rr + 1) * 18 + cc) = make_float2(a10, a11);
        }
        __syncthreads();

        // R4: warp0 solves S X = CSp
        if (tid < 32) {
            const int c = tid;
            float Sc[P], Rc[P];
            #pragma unroll
            for (int rr = 0; rr < P; rr++) {
                Sc[rr] = sS[rr * 18 + (c & 15)];
                Rc[rr] = sCSp[rr * MA + c];
            }
            #pragma unroll
            for (int j = 0; j < P; j++) {
                float fj = __shfl_sync(0xffffffffu, Sc[j], j);
                float pinv = 1.0f / fj;
                Sc[j] *= pinv; Rc[j] *= pinv;
                float sj = Sc[j], rj = Rc[j];
                #pragma unroll
                for (int rr = 0; rr < P; rr++) {
                    if (rr != j) {
                        float f = __shfl_sync(0xffffffffu, Sc[rr], j);
                        Sc[rr] -= f * sj; Rc[rr] -= f * rj;
                    }
                }
            }
            #pragma unroll
            for (int rr = 0; rr < P; rr++) sX[rr * MA + c] = Rc[rr];
        }
        __syncthreads();

        // R5: Sig_f = Sig_p - 0.5*(X^T CSp + CSp^T X) ; mu_f
        {
            float2 p0 = *(const float2*)(sSp + r0 * MA + c0);
            float2 p1 = *(const float2*)(sSp + (r0 + 1) * MA + c0);
            float m00 = 0, m01 = 0, m10 = 0, m11 = 0;
            #pragma unroll
            for (int j = 0; j < P; j++) {
                float2 xr = *(const float2*)(sX + j * MA + r0);
                float2 zr = *(const float2*)(sCSp + j * MA + r0);
                float2 xc = *(const float2*)(sX + j * MA + c0);
                float2 zc = *(const float2*)(sCSp + j * MA + c0);
                m00 += xr.x * zc.x + zr.x * xc.x;
                m01 += xr.x * zc.y + zr.x * xc.y;
                m10 += xr.y * zc.x + zr.y * xc.x;
                m11 += xr.y * zc.y + zr.y * xc.y;
            }
            float v00 = p0.x - 0.5f * m00, v01 = p0.y - 0.5f * m01;
            float v10 = p1.x - 0.5f * m10, v11 = p1.y - 0.5f * m11;
            *(float2*)(sSig + r0 * MA + c0) = make_float2(v00, v01);
            *(float2*)(sSig + (r0 + 1) * MA + c0) = make_float2(v10, v11);
            float* gf = g_Sigf + (bt << 10);
            *(float2*)(gf + r0 * 32 + c0) = make_float2(v00, v01);
            *(float2*)(gf + (r0 + 1) * 32 + c0) = make_float2(v10, v11);
        }
        if (tid < N) {
            float s = smup[tid];
            #pragma unroll
            for (int j = 0; j < P; j++) s += sX[j * MA + tid] * sd[j];
            smu[tid] = s;
            g_muf[bt * N + tid] = s;
        }
        __syncthreads();
    }
}

// =====================================================================
// Backward pipeline: verbatim 997.3us configuration.
// =====================================================================
__global__ __launch_bounds__(128) void k_J2(const float* __restrict__ A)
{
    const int t = blockIdx.x;
    const int b = blockIdx.y;
    const size_t bt = (size_t)b * T + t;
    const int tid = threadIdx.x;

    __shared__ __align__(16) float sA[NMA], sSf[NMA], sSp[NMA];
    __shared__ __align__(16) float sG[NMA], sXs[NMA];
    __shared__ float smf[N], smp[N];

    {
        const float2* Ab = (const float2*)(A + bt * (N * N));
        const float2* gf = (const float2*)(g_Sigf + (bt << 10));
        const float2* gp = (const float2*)(g_Sigp + ((bt + 1) << 10));
        for (int i2 = tid; i2 < 512; i2 += 128) {
            int r = i2 >> 4, c = (i2 & 15) * 2;
            *(float2*)(sA + r * MA + c) = Ab[i2];
            *(float2*)(sSf + r * MA + c) = gf[i2];
            *(float2*)(sSp + r * MA + c) = gp[i2];
        }
        if (tid < N) {
            smf[tid] = g_muf[bt * N + tid];
            smp[tid] = g_mup[(bt + 1) * N + tid];
        }
    }
    __syncthreads();

    #pragma unroll
    for (int s = 0; s < 2; s++) {
        const int id = tid + s * 128;
        const int r0 = (id >> 4) * 2, c0 = (id & 15) * 2;
        const float2* Xr0 = (const float2*)(sA + r0 * MA);
        const float2* Xr1 = (const float2*)(sA + (r0 + 1) * MA);
        float a00 = 0, a01 = 0, a10 = 0, a11 = 0;
        #pragma unroll
        for (int k2 = 0; k2 < 16; k2++) {
            float2 x0 = Xr0[k2], x1 = Xr1[k2];
            float2 y0 = *(const float2*)(sSf + (2 * k2) * MA + c0);
            float2 y1 = *(const float2*)(sSf + (2 * k2 + 1) * MA + c0);
            a00 += x0.x * y0.x + x0.y * y1.x;  a01 += x0.x * y0.y + x0.y * y1.y;
            a10 += x1.x * y0.x + x1.y * y1.x;  a11 += x1.x * y0.y + x1.y * y1.y;
        }
        *(float2*)(sG + r0 * MA + c0) = make_float2(a00, a01);
        *(float2*)(sG + (r0 + 1) * MA + c0) = make_float2(a10, a11);
    }
    __syncthreads();

    if (tid < 32) {
        const int c = tid;
        float Sc[N], Gc[N];
        #pragma unroll
        for (int rr = 0; rr < N; rr++) {
            Sc[rr] = sSp[rr * MA + c];
            Gc[rr] = sG[rr * MA + c];
        }
        #pragma unroll
        for (int j = 0; j < N; j++) {
            float fj = __shfl_sync(0xffffffffu, Sc[j], j);
            float pinv = 1.0f / fj;
            Sc[j] *= pinv;
            Gc[j] *= pinv;
            float scj = Sc[j], gcj = Gc[j];
            #pragma unroll
            for (int rr = 0; rr < N; rr++) {
                if (rr != j) {
                    float f = __shfl_sync(0xffffffffu, Sc[rr], j);
                    Sc[rr] -= f * scj;
                    Gc[rr] -= f * gcj;
                }
            }
        }
        #pragma unroll
        for (int rr = 0; rr < N; rr++) sXs[rr * MA + c] = Gc[rr];
    }
    __syncthreads();

    const size_t jidx = (size_t)b * (T - 1) + t;

    if (tid < N) {
        float s = smf[tid];
        #pragma unroll
        for (int kk = 0; kk < N; kk++) s -= sXs[kk * MA + tid] * smp[kk];
        g_c[jidx * N + tid] = s;
    }
    {
        float2* gj = (float2*)(g_J + jidx * (N * N));
        for (int i2 = tid; i2 < 512; i2 += 128) {
            int r = i2 >> 4, c = (i2 & 15) * 2;
            gj[i2] = *(const float2*)(sXs + r * MA + c);
        }
    }
    {
        float* gm = g_M + jidx * (N * N);
        #pragma unroll
        for (int s = 0; s < 2; s++) {
            const int id = tid + s * 128;
            const int r0 = (id >> 4) * 2, c0 = (id & 15) * 2;
            float2 f0 = *(const float2*)(sSf + r0 * MA + c0);
            float2 f1 = *(const float2*)(sSf + (r0 + 1) * MA + c0);
            float a00 = f0.x, a01 = f0.y, a10 = f1.x, a11 = f1.y;
            #pragma unroll
            for (int kk = 0; kk < N; kk++) {
                float x0 = sXs[kk * MA + r0], x1 = sXs[kk * MA + r0 + 1];
                float2 g = *(const float2*)(sG + kk * MA + c0);
                a00 -= x0 * g.x;  a01 -= x0 * g.y;
                a10 -= x1 * g.x;  a11 -= x1 * g.y;
            }
            *(float2*)(gm + r0 * 32 + c0) = make_float2(a00, a01);
            *(float2*)(gm + (r0 + 1) * 32 + c0) = make_float2(a10, a11);
        }
    }
}

__global__ __launch_bounds__(256) void k_scanA()
{
    const int k = blockIdx.x, b = blockIdx.y;
    const int t_lo = CHS * k;
    const int t_hi = (k == NCH - 1) ? (T - 2) : (CHS * k + CHS - 1);
    const int tid = threadIdx.x;

    __shared__ __align__(16) float sXO[NMA], sMO[NMA];
    __shared__ __align__(16) float sXt[2][NMA], sMt[2][NMA];
    __shared__ __align__(16) float sW[NMA], sXN[NMA];
    __shared__ float scO[N], sct[2][N], scN[N];

    const int r0 = (tid >> 4) * 2, c0 = (tid & 15) * 2;
    const int ra = tid >> 4, ca = (tid & 15) * 2;
    const int rb = ra + 16;

    {
        const size_t base = (size_t)b * (T - 1) + t_hi;
        const float2* gx = (const float2*)(g_J + base * (N * N));
        const float2* gm = (const float2*)(g_M + base * (N * N));
        for (int i2 = tid; i2 < 512; i2 += 256) {
            int r = i2 >> 4, c = (i2 & 15) * 2;
            *(float2*)(sXO + r * MA + c) = gx[i2];
            *(float2*)(sMO + r * MA + c) = gm[i2];
        }
        if (tid < N) scO[tid] = g_c[base * N + tid];
    }

    float2 pX0, pX1, pM0, pM1;
    float pc = 0.f;
    if (t_hi - 1 >= t_lo) {
        const size_t base = (size_t)b * (T - 1) + (t_hi - 1);
        const float2* gx = (const float2*)(g_J + base * (N * N));
        const float2* gm = (const float2*)(g_M + base * (N * N));
        pX0 = gx[tid];  pX1 = gx[tid + 256];
        pM0 = gm[tid];  pM1 = gm[tid + 256];
        if (tid < N) pc = g_c[base * N + tid];
    }
    __syncthreads();

    for (int t = t_hi - 1; t >= t_lo; t--) {
        const int buf = (t_hi - 1 - t) & 1;
        *(float2*)(sXt[buf] + ra * MA + ca) = pX0;
        *(float2*)(sXt[buf] + rb * MA + ca) = pX1;
        *(float2*)(sMt[buf] + ra * MA + ca) = pM0;
        *(float2*)(sMt[buf] + rb * MA + ca) = pM1;
        if (tid < N) sct[buf][tid] = pc;
        if (t > t_lo) {
            const size_t base = (size_t)b * (T - 1) + (t - 1);
            const float2* gx = (const float2*)(g_J + base * (N * N));
            const float2* gm = (const float2*)(g_M + base * (N * N));
            pX0 = gx[tid];  pX1 = gx[tid + 256];
            pM0 = gm[tid];  pM1 = gm[tid + 256];
            if (tid < N) pc = g_c[base * N + tid];
        }
        __syncthreads();

        const float* Xt = sXt[buf];
        const float* Mt = sMt[buf];

        {
            const float2* Mr0 = (const float2*)(sMO + r0 * MA);
            const float2* Mr1 = (const float2*)(sMO + (r0 + 1) * MA);
            const float2* Or0 = (const float2*)(sXO + r0 * MA);
            const float2* Or1 = (const float2*)(sXO + (r0 + 1) * MA);
            float w00 = 0, w01 = 0, w10 = 0, w11 = 0;
            float x00 = 0, x01 = 0, x10 = 0, x11 = 0;
            #pragma unroll
            for (int k2 = 0; k2 < 16; k2++) {
                float2 y0 = *(const float2*)(Xt + (2 * k2) * MA + c0);
                float2 y1 = *(const float2*)(Xt + (2 * k2 + 1) * MA + c0);
                float2 m0 = Mr0[k2], m1 = Mr1[k2];
                float2 o0 = Or0[k2], o1 = Or1[k2];
                w00 += m0.x * y0.x + m0.y * y1.x;  w01 += m0.x * y0.y + m0.y * y1.y;
                w10 += m1.x * y0.x + m1.y * y1.x;  w11 += m1.x * y0.y + m1.y * y1.y;
                x00 += o0.x * y0.x + o0.y * y1.x;  x01 += o0.x * y0.y + o0.y * y1.y;
                x10 += o1.x * y0.x + o1.y * y1.x;  x11 += o1.x * y0.y + o1.y * y1.y;
            }
            *(float2*)(sW + r0 * MA + c0) = make_float2(w00, w01);
            *(float2*)(sW + (r0 + 1) * MA + c0) = make_float2(w10, w11);
            *(float2*)(sXN + r0 * MA + c0) = make_float2(x00, x01);
            *(float2*)(sXN + (r0 + 1) * MA + c0) = make_float2(x10, x11);
        }
        if (tid < N) {
            float s = sct[buf][tid];
            #pragma unroll
            for (int j = 0; j < N; j++) s += Xt[j * MA + tid] * scO[j];
            scN[tid] = s;
        }
        __syncthreads();

        {
            float2 f0 = *(const float2*)(Mt + r0 * MA + c0);
            float2 f1 = *(const float2*)(Mt + (r0 + 1) * MA + c0);
            float a00 = f0.x, a01 = f0.y, a10 = f1.x, a11 = f1.y;
            #pragma unroll
            for (int j = 0; j < N; j++) {
                float2 xj = *(const float2*)(Xt + j * MA + r0);
                float2 wj = *(const float2*)(sW + j * MA + c0);
                a00 += xj.x * wj.x;  a01 += xj.x * wj.y;
                a10 += xj.y * wj.x;  a11 += xj.y * wj.y;
            }
            *(float2*)(sMO + r0 * MA + c0) = make_float2(a00, a01);
            *(float2*)(sMO + (r0 + 1) * MA + c0) = make_float2(a10, a11);
            *(float2*)(sXO + r0 * MA + c0) = *(const float2*)(sXN + r0 * MA + c0);
            *(float2*)(sXO + (r0 + 1) * MA + c0) = *(const float2*)(sXN + (r0 + 1) * MA + c0);
        }
        if (tid < N) scO[tid] = scN[tid];
        __syncthreads();
    }

    {
        const size_t obase = (size_t)b * NCH + k;
        float2* gx = (float2*)(g_OX + obase * (N * N));
        float2* gm = (float2*)(g_OM + obase * (N * N));
        for (int i2 = tid; i2 < 512; i2 += 256) {
            int r = i2 >> 4, c = (i2 & 15) * 2;
            gx[i2] = *(const float2*)(sXO + r * MA + c);
            gm[i2] = *(const float2*)(sMO + r * MA + c);
        }
        if (tid < N) g_Oc[obase * N + tid] = scO[tid];
    }
}

__global__ __launch_bounds__(256) void k_scanB(float* __restrict__ out)
{
    const int b = blockIdx.x;
    const int tid = threadIdx.x;

    __shared__ __align__(16) float sS[NMA], sX[NMA], sMm[NMA], sW[NMA];
    __shared__ float smu[N], smuN[N], sc[N];

    const int r0 = (tid >> 4) * 2, c0 = (tid & 15) * 2;

    {
        const size_t btL = (size_t)b * T + (T - 1);
        const float2* gf = (const float2*)(g_Sigf + (btL << 10));
        float2* ge = (float2*)(g_eS + ((size_t)b * NCH + (NCH - 1)) * (N * N));
        for (int i2 = tid; i2 < 512; i2 += 256) {
            int r = i2 >> 4, c = (i2 & 15) * 2;
            float2 v = gf[i2];
            *(float2*)(sS + r * MA + c) = v;
            ge[i2] = v;
            float* o = out + (btL * N + r) * (N + 1) + 1 + c;
            o[0] = v.x; o[1] = v.y;
        }
        if (tid < N) {
            float v = g_muf[btL * N + tid];
            smu[tid] = v;
            g_emu[((size_t)b * NCH + (NCH - 1)) * N + tid] = v;
            out[(btL * N + tid) * (N + 1)] = v;
        }
    }
    __syncthreads();

    for (int k = NCH - 2; k >= 0; k--) {
        const size_t obase = (size_t)b * NCH + (k + 1);
        {
            const float2* gx = (const float2*)(g_OX + obase * (N * N));
            const float2* gm = (const float2*)(g_OM + obase * (N * N));
            for (int i2 = tid; i2 < 512; i2 += 256) {
                int r = i2 >> 4, c = (i2 & 15) * 2;
                *(float2*)(sX + r * MA + c) = gx[i2];
                *(float2*)(sMm + r * MA + c) = gm[i2];
            }
            if (tid < N) sc[tid] = g_Oc[obase * N + tid];
        }
        __syncthreads();

        {
            const float2* Sr0 = (const float2*)(sS + r0 * MA);
            const float2* Sr1 = (const float2*)(sS + (r0 + 1) * MA);
            float a00 = 0, a01 = 0, a10 = 0, a11 = 0;
            #pragma unroll
            for (int k2 = 0; k2 < 16; k2++) {
                float2 x0 = Sr0[k2], x1 = Sr1[k2];
                float2 y0 = *(const float2*)(sX + (2 * k2) * MA + c0);
                float2 y1 = *(const float2*)(sX + (2 * k2 + 1) * MA + c0);
                a00 += x0.x * y0.x + x0.y * y1.x;  a01 += x0.x * y0.y + x0.y * y1.y;
                a10 += x1.x * y0.x + x1.y * y1.x;  a11 += x1.x * y0.y + x1.y * y1.y;
            }
            *(float2*)(sW + r0 * MA + c0) = make_float2(a00, a01);
            *(float2*)(sW + (r0 + 1) * MA + c0) = make_float2(a10, a11);
        }
        if (tid < N) {
            float s = sc[tid];
            #pragma unroll
            for (int j = 0; j < N; j++) s += sX[j * MA + tid] * smu[j];
            smuN[tid] = s;
        }
        __syncthreads();

        {
            float2 f0 = *(const float2*)(sMm + r0 * MA + c0);
            float2 f1 = *(const float2*)(sMm + (r0 + 1) * MA + c0);
            float a00 = f0.x, a01 = f0.y, a10 = f1.x, a11 = f1.y;
            #pragma unroll
            for (int j = 0; j < N; j++) {
                float2 xj = *(const float2*)(sX + j * MA + r0);
                float2 wj = *(const float2*)(sW + j * MA + c0);
                a00 += xj.x * wj.x;  a01 += xj.x * wj.y;
                a10 += xj.y * wj.x;  a11 += xj.y * wj.y;
            }
            *(float2*)(sS + r0 * MA + c0) = make_float2(a00, a01);
            *(float2*)(sS + (r0 + 1) * MA + c0) = make_float2(a10, a11);
            float* ge = g_eS + ((size_t)b * NCH + k) * (N * N);
            *(float2*)(ge + r0 * 32 + c0) = make_float2(a00, a01);
            *(float2*)(ge + (r0 + 1) * 32 + c0) = make_float2(a10, a11);
        }
        if (tid < N) {
            smu[tid] = smuN[tid];
            g_emu[((size_t)b * NCH + k) * N + tid] = smuN[tid];
        }
        __syncthreads();
    }
}

__global__ __launch_bounds__(256) void k_scanC(float* __restrict__ out)
{
    const int k = blockIdx.x, b = blockIdx.y;
    const int t_lo = CHS * k;
    const int t_hi = (k == NCH - 1) ? (T - 2) : (CHS * k + CHS - 1);
    const int tid = threadIdx.x;

    __shared__ __align__(16) float sS[NMA], sW[NMA];
    __shared__ __align__(16) float sX[2][NMA], sMm[2][NMA];
    __shared__ float smu[N], smuN[N], sc[2][N];

    const int r0 = (tid >> 4) * 2, c0 = (tid & 15) * 2;
    const int ra = tid >> 4, ca = (tid & 15) * 2;
    const int rb = ra + 16;

    {
        const size_t ebase = (size_t)b * NCH + k;
        const float2* ge = (const float2*)(g_eS + ebase * (N * N));
        for (int i2 = tid; i2 < 512; i2 += 256) {
            int r = i2 >> 4, c = (i2 & 15) * 2;
            *(float2*)(sS + r * MA + c) = ge[i2];
        }
        if (tid < N) smu[tid] = g_emu[ebase * N + tid];
    }

    float2 pX0, pX1, pM0, pM1;
    float pc = 0.f;
    {
        const size_t base = (size_t)b * (T - 1) + t_hi;
        const float2* gx = (const float2*)(g_J + base * (N * N));
        const float2* gm = (const float2*)(g_M + base * (N * N));
        pX0 = gx[tid];  pX1 = gx[tid + 256];
        pM0 = gm[tid];  pM1 = gm[tid + 256];
        if (tid < N) pc = g_c[base * N + tid];
    }
    __syncthreads();

    for (int t = t_hi; t >= t_lo; t--) {
        const int buf = (t_hi - t) & 1;
        const size_t bt = (size_t)b * T + t;
        *(float2*)(sX[buf] + ra * MA + ca) = pX0;
        *(float2*)(sX[buf] + rb * MA + ca) = pX1;
        *(float2*)(sMm[buf] + ra * MA + ca) = pM0;
        *(float2*)(sMm[buf] + rb * MA + ca) = pM1;
        if (tid < N) sc[buf][tid] = pc;
        if (t > t_lo) {
            const size_t base = (size_t)b * (T - 1) + (t - 1);
            const float2* gx = (const float2*)(g_J + base * (N * N));
            const float2* gm = (const float2*)(g_M + base * (N * N));
            pX0 = gx[tid];  pX1 = gx[tid + 256];
            pM0 = gm[tid];  pM1 = gm[tid + 256];
            if (tid < N) pc = g_c[base * N + tid];
        }
        __syncthreads();

        const float* Xb = sX[buf];
        const float* Mb = sMm[buf];

        {
            const float2* Sr0 = (const float2*)(sS + r0 * MA);
            const float2* Sr1 = (const float2*)(sS + (r0 + 1) * MA);
            float a00 = 0, a01 = 0, a10 = 0, a11 = 0;
            #pragma unroll
            for (int k2 = 0; k2 < 16; k2++) {
                float2 x0 = Sr0[k2], x1 = Sr1[k2];
                float2 y0 = *(const float2*)(Xb + (2 * k2) * MA + c0);
                float2 y1 = *(const float2*)(Xb + (2 * k2 + 1) * MA + c0);
                a00 += x0.x * y0.x + x0.y * y1.x;  a01 += x0.x * y0.y + x0.y * y1.y;
                a10 += x1.x * y0.x + x1.y * y1.x;  a11 += x1.x * y0.y + x1.y * y1.y;
            }
            *(float2*)(sW + r0 * MA + c0) = make_float2(a00, a01);
            *(float2*)(sW + (r0 + 1) * MA + c0) = make_float2(a10, a11);
        }
        if (tid < N) {
            float s = sc[buf][tid];
            #pragma unroll
            for (int j = 0; j < N; j++) s += Xb[j * MA + tid] * smu[j];
            smuN[tid] = s;
        }
        __syncthreads();

        {
            float2 f0 = *(const float2*)(Mb + r0 * MA + c0);
            float2 f1 = *(const float2*)(Mb + (r0 + 1) * MA + c0);
            float a00 = f0.x, a01 = f0.y, a10 = f1.x, a11 = f1.y;
            #pragma unroll
            for (int j = 0; j < N; j++) {
                float2 xj = *(const float2*)(Xb + j * MA + r0);
                float2 wj = *(const float2*)(sW + j * MA + c0);
                a00 += xj.x * wj.x;  a01 += xj.x * wj.y;
                a10 += xj.y * wj.x;  a11 += xj.y * wj.y;
            }
            *(float2*)(sS + r0 * MA + c0) = make_float2(a00, a01);
            *(float2*)(sS + (r0 + 1) * MA + c0) = make_float2(a10, a11);
            float* o = out + (bt * N + r0) * (N + 1) + 1 + c0;
            o[0] = a00; o[1] = a01;
            o[N + 1] = a10; o[N + 2] = a11;
        }
        if (tid < N) {
            smu[tid] = smuN[tid];
            out[(bt * N + tid) * (N + 1)] = smuN[tid];
        }
        __syncthreads();
    }
}

extern "C" void kernel_launch(void* const* d_in, const int* in_sizes, int n_in,
                              void* d_out, int out_size) {
    (void)in_sizes; (void)n_in; (void)out_size;
    const float* Y   = (const float*)d_in[0];
    const float* U   = (const float*)d_in[1];
    const float* A   = (const float*)d_in[2];
    const float* Bm  = (const float*)d_in[3];
    const float* C   = (const float*)d_in[4];
    const float* mu0 = (const float*)d_in[5];
    const float* S0  = (const float*)d_in[6];
    float* out = (float*)d_out;

    static int attr_set = 0;
    if (!attr_set) {
        cudaFuncSetAttribute(kFA, cudaFuncAttributeMaxDynamicSharedMemorySize,
                             FA_BYTES);
        attr_set = 1;
    }

    kE<<<dim3(T, BATCH), 128>>>(Y, U, A, Bm, C);
    kFA<<<dim3(NCHF, BATCH), 256, FA_BYTES>>>();
    kFB<<<BATCH, 256>>>(mu0, S0);
    kFC<<<dim3(NCHF, BATCH), 256>>>(Y, U, A, Bm, C);
    k_J2<<<dim3(T - 1, BATCH), 128>>>(A);
    k_scanA<<<dim3(NCH, BATCH), 256>>>();
    k_scanB<<<BATCH, 256>>>(out);
    k_scanC<<<dim3(NCH, BATCH), 256>>>(out);
}

// round 14
// speedup vs baseline: 1.3406x; 1.3406x over previous
#include <cuda_runtime.h>

#define BATCH 64
#define T 128
#define N 32
#define M 8
#define P 16
#define MA 34    // padded row stride (even -> float2-aligned rows)
#define NCH 16   // backward-scan chunks
#define CHS 8    // chunk size
#define NTF 512  // k_fwd threads
#define NSL 8    // forward slices
#define SLT 16   // steps per slice

// Global scratch
__device__ float g_muf[BATCH * T * N];
__device__ float g_mup[BATCH * T * N];
__device__ float g_Sigf[(size_t)BATCH * T * N * N];
__device__ float g_Sigp[(size_t)BATCH * T * N * N];
__device__ float g_J[(size_t)BATCH * (T - 1) * N * N];   // X_t = J_t^T
__device__ float g_M[(size_t)BATCH * (T - 1) * N * N];   // M_t
__device__ float g_c[(size_t)BATCH * (T - 1) * N];       // c_t
__device__ float g_OX[(size_t)BATCH * NCH * N * N];
__device__ float g_OM[(size_t)BATCH * NCH * N * N];
__device__ float g_Oc[(size_t)BATCH * NCH * N];
__device__ float g_eS[(size_t)BATCH * NCH * N * N];
__device__ float g_emu[(size_t)BATCH * NCH * N];
// forward slice state carry
__device__ float g_sMu[BATCH * N];
__device__ float g_sSig[(size_t)BATCH * N * N];

// =====================================================================
// Kernel 1: forward Kalman filter slice [t0, t1). Proven 997.3 step body.
// =====================================================================
__global__ __launch_bounds__(NTF, 1) void k_fwd(
    const float* __restrict__ Y, const float* __restrict__ U,
    const float* __restrict__ A, const float* __restrict__ Bm,
    const float* __restrict__ C, const float* __restrict__ mu0,
    const float* __restrict__ Sig0, int t0, int t1)
{
    const int b = blockIdx.x;
    const int tid = threadIdx.x;

    __shared__ __align__(16) float sA[2][N * MA];
    __shared__ __align__(16) float sC[2][P * MA];
    __shared__ __align__(16) float sB[2][N * M];
    __shared__ float sy[2][P], su[2][M];
    __shared__ __align__(16) float sSig[N * MA], sAS[N * MA], sSigp[N * MA];
    __shared__ __align__(16) float sV[P * MA], sZ[P * MA], sCSp[P * MA];
    __shared__ __align__(16) float sS[P * 18];
    __shared__ __align__(16) float sX[P * MA];     // X = K^T (16 x 32)
    __shared__ float smu[N], smup[N], sd[P];

    // ---- init state (prior or carried) + slice-start inputs ----
    if (t0 == 0) {
        if (tid < N) smu[tid] = mu0[tid];
        for (int i2 = tid; i2 < 512; i2 += NTF) {
            int r = i2 >> 4, c2 = i2 & 15;
            *(float2*)(sSig + r * MA + 2 * c2) = ((const float2*)Sig0)[i2];
        }
    } else {
        if (tid < N) smu[tid] = g_sMu[b * N + tid];
        const float2* gs = (const float2*)(g_sSig + (size_t)b * (N * N));
        for (int i2 = tid; i2 < 512; i2 += NTF) {
            int r = i2 >> 4, c2 = i2 & 15;
            *(float2*)(sSig + r * MA + 2 * c2) = gs[i2];
        }
    }
    {
        const size_t bt = (size_t)b * T + t0;
        const float2* Ab = (const float2*)(A + bt * (N * N));
        const float2* Cb = (const float2*)(C + bt * (P * N));
        const float2* Bb = (const float2*)(Bm + bt * (N * M));
        for (int i2 = tid; i2 < 512; i2 += NTF) {
            int r = i2 >> 4, c2 = i2 & 15;
            *(float2*)(sA[0] + r * MA + 2 * c2) = Ab[i2];
        }
        if (tid < 256) {
            int r = tid >> 4, c2 = tid & 15;
            *(float2*)(sC[0] + r * MA + 2 * c2) = Cb[tid];
        }
        if (tid < 128) ((float2*)sB[0])[tid] = Bb[tid];
        if (tid < P) sy[0][tid] = Y[bt * P + tid];
        if (tid < M) su[0][tid] = U[bt * M + tid];
    }
    __syncthreads();

    for (int t = t0; t < t1; t++) {
        const int cur = (t - t0) & 1, nxt = cur ^ 1;
        const size_t bt = (size_t)b * T + t;
        const float* Ac = sA[cur];
        const float* Cc = sC[cur];

        // ================= R0: AS = A*Sig (2x2) | V = C*A (1x2) + mu_p ======
        if (tid < 256) {
            const int r0 = (tid >> 4) * 2, c0 = (tid & 15) * 2;
            const float2* Xr0 = (const float2*)(Ac + r0 * MA);
            const float2* Xr1 = (const float2*)(Ac + (r0 + 1) * MA);
            float a00 = 0, a01 = 0, a10 = 0, a11 = 0;
            #pragma unroll
            for (int k2 = 0; k2 < 16; k2++) {
                float2 x0 = Xr0[k2], x1 = Xr1[k2];
                float2 y0 = *(const float2*)(sSig + (2 * k2) * MA + c0);
                float2 y1 = *(const float2*)(sSig + (2 * k2 + 1) * MA + c0);
                a00 += x0.x * y0.x + x0.y * y1.x;  a01 += x0.x * y0.y + x0.y * y1.y;
                a10 += x1.x * y0.x + x1.y * y1.x;  a11 += x1.x * y0.y + x1.y * y1.y;
            }
            *(float2*)(sAS + r0 * MA + c0) = make_float2(a00, a01);
            *(float2*)(sAS + (r0 + 1) * MA + c0) = make_float2(a10, a11);
        } else {
            const int id = tid - 256;
            const int i = id >> 4, j0 = (id & 15) * 2;
            const float2* Cr = (const float2*)(Cc + i * MA);
            float a0 = 0, a1 = 0;
            #pragma unroll
            for (int k2 = 0; k2 < 16; k2++) {
                float2 cv = Cr[k2];
                float2 y0 = *(const float2*)(Ac + (2 * k2) * MA + j0);
                float2 y1 = *(const float2*)(Ac + (2 * k2 + 1) * MA + j0);
                a0 += cv.x * y0.x + cv.y * y1.x;
                a1 += cv.x * y0.y + cv.y * y1.y;
            }
            *(float2*)(sV + i * MA + j0) = make_float2(a0, a1);
            if (id < 32) {      // mu_p for state row id
                const float2* Ar = (const float2*)(Ac + id * MA);
                float s = 0.f;
                #pragma unroll
                for (int j = 0; j < 16; j++) {
                    float2 a = Ar[j];
                    s += a.x * smu[2 * j] + a.y * smu[2 * j + 1];
                }
                const float2* Br = (const float2*)(sB[cur] + id * M);
                #pragma unroll
                for (int j = 0; j < 4; j++) {
                    float2 bb = Br[j];
                    s += bb.x * su[cur][2 * j] + bb.y * su[cur][2 * j + 1];
                }
                smup[id] = s;
                g_mup[bt * N + id] = s;
            }
        }
        __syncthreads();

        // ================= R1: Sig_p = AS*A^T + Q (2x2) | Z = V*Sig (1x2) ===
        if (tid < 256) {
            const int r0 = (tid >> 4) * 2, c0 = (tid & 15) * 2;
            const float2* Xr0 = (const float2*)(sAS + r0 * MA);
            const float2* Xr1 = (const float2*)(sAS + (r0 + 1) * MA);
            const float2* Yc0 = (const float2*)(Ac + c0 * MA);
            const float2* Yc1 = (const float2*)(Ac + (c0 + 1) * MA);
            float a00 = (r0 == c0) ? 0.01f : 0.f, a01 = 0, a10 = 0;
            float a11 = (r0 == c0) ? 0.01f : 0.f;
            #pragma unroll
            for (int k2 = 0; k2 < 16; k2++) {
                float2 x0 = Xr0[k2], x1 = Xr1[k2], y0 = Yc0[k2], y1 = Yc1[k2];
                a00 += x0.x * y0.x + x0.y * y0.y;  a01 += x0.x * y1.x + x0.y * y1.y;
                a10 += x1.x * y0.x + x1.y * y0.y;  a11 += x1.x * y1.x + x1.y * y1.y;
            }
            *(float2*)(sSigp + r0 * MA + c0) = make_float2(a00, a01);
            *(float2*)(sSigp + (r0 + 1) * MA + c0) = make_float2(a10, a11);
        } else {
            const int id = tid - 256;
            const int i = id >> 4, j0 = (id & 15) * 2;
            const float2* Vr = (const float2*)(sV + i * MA);
            float a0 = 0, a1 = 0;
            #pragma unroll
            for (int k2 = 0; k2 < 16; k2++) {
                float2 v = Vr[k2];
                float2 y0 = *(const float2*)(sSig + (2 * k2) * MA + j0);
                float2 y1 = *(const float2*)(sSig + (2 * k2 + 1) * MA + j0);
                a0 += v.x * y0.x + v.y * y1.x;
                a1 += v.x * y0.y + v.y * y1.y;
            }
            *(float2*)(sZ + i * MA + j0) = make_float2(a0, a1);
        }
        __syncthreads();

        // ==== R2: CSp = Z*A^T + 0.01C | S = Z*V^T + 0.01CC^T + R | resid | STG
        if (tid < 256) {
            const int i = tid >> 4, j0 = (tid & 15) * 2;
            const float2* Zr = (const float2*)(sZ + i * MA);
            const float2* Aj0 = (const float2*)(Ac + j0 * MA);
            const float2* Aj1 = (const float2*)(Ac + (j0 + 1) * MA);
            float2 cv = *(const float2*)(Cc + i * MA + j0);
            float a0 = 0.01f * cv.x, a1 = 0.01f * cv.y;
            #pragma unroll
            for (int k2 = 0; k2 < 16; k2++) {
                float2 z = Zr[k2], y0 = Aj0[k2], y1 = Aj1[k2];
                a0 += z.x * y0.x + z.y * y0.y;
                a1 += z.x * y1.x + z.y * y1.y;
            }
            *(float2*)(sCSp + i * MA + j0) = make_float2(a0, a1);
        } else if (tid < 384) {
            const int id = tid - 256;
            const int i = id >> 3, j0 = (id & 7) * 2;
            const float2* Zr = (const float2*)(sZ + i * MA);
            const float2* Ci = (const float2*)(Cc + i * MA);
            const float2* Vj0 = (const float2*)(sV + j0 * MA);
            const float2* Vj1 = (const float2*)(sV + (j0 + 1) * MA);
            const float2* Cj0 = (const float2*)(Cc + j0 * MA);
            const float2* Cj1 = (const float2*)(Cc + (j0 + 1) * MA);
            float a0 = (i == j0) ? 0.01f : 0.f;
            float a1 = (i == j0 + 1) ? 0.01f : 0.f;
            #pragma unroll
            for (int k2 = 0; k2 < 16; k2++) {
                float2 z = Zr[k2], ci = Ci[k2];
                float2 v0 = Vj0[k2], v1 = Vj1[k2];
                float2 c0v = Cj0[k2], c1v = Cj1[k2];
                a0 += z.x * v0.x + z.y * v0.y + 0.01f * (ci.x * c0v.x + ci.y * c0v.y);
                a1 += z.x * v1.x + z.y * v1.y + 0.01f * (ci.x * c1v.x + ci.y * c1v.y);
            }
            *(float2*)(sS + i * 18 + j0) = make_float2(a0, a1);
        } else if (tid < 400) {
            const int i = tid - 384;
            const float2* Cr = (const float2*)(Cc + i * MA);
            float s = sy[cur][i];
            #pragma unroll
            for (int j = 0; j < 16; j++) {
                float2 cv = Cr[j];
                s -= cv.x * smup[2 * j] + cv.y * smup[2 * j + 1];
            }
            sd[i] = s;
        } else {
            float2* gp = (float2*)(g_Sigp + (bt << 10));
            for (int i2 = tid - 400; i2 < 512; i2 += 112) {
                int rr = i2 >> 4, c2 = i2 & 15;
                gp[i2] = *(const float2*)(sSigp + rr * MA + 2 * c2);
            }
        }
        __syncthreads();

        // ================= R3: warp0 solves S X = CSp | others prefetch t+1 =
        if (tid < 32) {
            const int c = tid;
            float Sc[P], Rc[P], piv[P];
            #pragma unroll
            for (int rr = 0; rr < P; rr++) {
                Sc[rr] = sS[rr * 18 + (c & 15)];
                Rc[rr] = sCSp[rr * MA + c];
            }
            #pragma unroll
            for (int j = 0; j < P; j++) {
                float f[P];
                #pragma unroll
                for (int rr = 0; rr < P; rr++) f[rr] = __shfl_sync(0xffffffffu, Sc[rr], j);
                float pinv = 1.0f / f[j];
                piv[j] = f[j];
                float sj = Sc[j] * pinv, rj = Rc[j] * pinv;
                #pragma unroll
                for (int rr = 0; rr < P; rr++) {
                    if (rr != j) { Sc[rr] -= f[rr] * sj; Rc[rr] -= f[rr] * rj; }
                }
            }
            #pragma unroll
            for (int rr = 0; rr < P; rr++) sX[rr * MA + c] = Rc[rr] / piv[rr];
        } else if (t + 1 < t1) {
            const int pt = tid - 32;
            const size_t bt1 = bt + 1;
            const float2* An = (const float2*)(A + bt1 * (N * N));
            const float2* Cn = (const float2*)(C + bt1 * (P * N));
            const float2* Bn = (const float2*)(Bm + bt1 * (N * M));
            for (int i2 = pt; i2 < 512; i2 += 480) {
                int rr = i2 >> 4, c2 = i2 & 15;
                *(float2*)(sA[nxt] + rr * MA + 2 * c2) = An[i2];
            }
            if (pt < 256) {
                int rr = pt >> 4, c2 = pt & 15;
                *(float2*)(sC[nxt] + rr * MA + 2 * c2) = Cn[pt];
            }
            if (pt < 128) ((float2*)sB[nxt])[pt] = Bn[pt];
            if (pt < P) sy[nxt][pt] = Y[bt1 * P + pt];
            else if (pt < P + M) su[nxt][pt - P] = U[bt1 * M + (pt - P)];
        }
        __syncthreads();

        // ===== R4: Sf = Sigp - 0.5*(X^T CSp + CSp^T X) (2x2, fused sym) | mu_f
        if (tid < 256) {
            const int r0 = (tid >> 4) * 2, c0 = (tid & 15) * 2;
            float2 p0 = *(const float2*)(sSigp + r0 * MA + c0);
            float2 p1 = *(const float2*)(sSigp + (r0 + 1) * MA + c0);
            float m00 = 0, m01 = 0, m10 = 0, m11 = 0;
            #pragma unroll
            for (int j = 0; j < P; j++) {
                float2 xr = *(const float2*)(sX + j * MA + r0);
                float2 zr = *(const float2*)(sCSp + j * MA + r0);
                float2 xc = *(const float2*)(sX + j * MA + c0);
                float2 zc = *(const float2*)(sCSp + j * MA + c0);
                m00 += xr.x * zc.x + zr.x * xc.x;
                m01 += xr.x * zc.y + zr.x * xc.y;
                m10 += xr.y * zc.x + zr.y * xc.x;
                m11 += xr.y * zc.y + zr.y * xc.y;
            }
            float v00 = p0.x - 0.5f * m00, v01 = p0.y - 0.5f * m01;
            float v10 = p1.x - 0.5f * m10, v11 = p1.y - 0.5f * m11;
            *(float2*)(sSig + r0 * MA + c0) = make_float2(v00, v01);
            *(float2*)(sSig + (r0 + 1) * MA + c0) = make_float2(v10, v11);
            float* gf = g_Sigf + (bt << 10);
            *(float2*)(gf + r0 * 32 + c0) = make_float2(v00, v01);
            *(float2*)(gf + (r0 + 1) * 32 + c0) = make_float2(v10, v11);
        } else if (tid < 288) {
            const int i = tid - 256;
            float s = smup[i];
            #pragma unroll
            for (int j = 0; j < P; j++) s += sX[j * MA + i] * sd[j];
            smu[i] = s;
            g_muf[bt * N + i] = s;
        }
        __syncthreads();
    }

    // ---- save carried state for next slice ----
    if (t1 < T) {
        if (tid < N) g_sMu[b * N + tid] = smu[tid];
        float2* gs = (float2*)(g_sSig + (size_t)b * (N * N));
        for (int i2 = tid; i2 < 512; i2 += NTF) {
            int r = i2 >> 4, c2 = i2 & 15;
            gs[i2] = *(const float2*)(sSig + r * MA + 2 * c2);
        }
    }
}

// =====================================================================
// Kernel 2: X_t, M_t, c_t for t in [t_base, t_base+gridDim.x). 128 thr.
// =====================================================================
__global__ __launch_bounds__(128) void k_J2(const float* __restrict__ A, int t_base)
{
    const int t = t_base + blockIdx.x;
    const int b = blockIdx.y;
    const size_t bt = (size_t)b * T + t;
    const int tid = threadIdx.x;

    __shared__ __align__(16) float sA[N * MA], sSf[N * MA], sSp[N * MA];
    __shared__ __align__(16) float sG[N * MA], sXs[N * MA];
    __shared__ float smf[N], smp[N];

    {
        const float2* Ab = (const float2*)(A + bt * (N * N));
        const float2* gf = (const float2*)(g_Sigf + (bt << 10));
        const float2* gp = (const float2*)(g_Sigp + ((bt + 1) << 10));
        for (int i2 = tid; i2 < 512; i2 += 128) {
            int r = i2 >> 4, c = (i2 & 15) * 2;
            *(float2*)(sA + r * MA + c) = Ab[i2];
            *(float2*)(sSf + r * MA + c) = gf[i2];
            *(float2*)(sSp + r * MA + c) = gp[i2];
        }
        if (tid < N) {
            smf[tid] = g_muf[bt * N + tid];
            smp[tid] = g_mup[(bt + 1) * N + tid];
        }
    }
    __syncthreads();

    #pragma unroll
    for (int s = 0; s < 2; s++) {
        const int id = tid + s * 128;
        const int r0 = (id >> 4) * 2, c0 = (id & 15) * 2;
        const float2* Xr0 = (const float2*)(sA + r0 * MA);
        const float2* Xr1 = (const float2*)(sA + (r0 + 1) * MA);
        float a00 = 0, a01 = 0, a10 = 0, a11 = 0;
        #pragma unroll
        for (int k2 = 0; k2 < 16; k2++) {
            float2 x0 = Xr0[k2], x1 = Xr1[k2];
            float2 y0 = *(const float2*)(sSf + (2 * k2) * MA + c0);
            float2 y1 = *(const float2*)(sSf + (2 * k2 + 1) * MA + c0);
            a00 += x0.x * y0.x + x0.y * y1.x;  a01 += x0.x * y0.y + x0.y * y1.y;
            a10 += x1.x * y0.x + x1.y * y1.x;  a11 += x1.x * y0.y + x1.y * y1.y;
        }
        *(float2*)(sG + r0 * MA + c0) = make_float2(a00, a01);
        *(float2*)(sG + (r0 + 1) * MA + c0) = make_float2(a10, a11);
    }
    __syncthreads();

    if (tid < 32) {
        const int c = tid;
        float Sc[N], Gc[N];
        #pragma unroll
        for (int rr = 0; rr < N; rr++) {
            Sc[rr] = sSp[rr * MA + c];
            Gc[rr] = sG[rr * MA + c];
        }
        #pragma unroll
        for (int j = 0; j < N; j++) {
            float fj = __shfl_sync(0xffffffffu, Sc[j], j);
            float pinv = 1.0f / fj;
            Sc[j] *= pinv;
            Gc[j] *= pinv;
            float scj = Sc[j], gcj = Gc[j];
            #pragma unroll
            for (int rr = 0; rr < N; rr++) {
                if (rr != j) {
                    float f = __shfl_sync(0xffffffffu, Sc[rr], j);
                    Sc[rr] -= f * scj;
                    Gc[rr] -= f * gcj;
                }
            }
        }
        #pragma unroll
        for (int rr = 0; rr < N; rr++) sXs[rr * MA + c] = Gc[rr];
    }
    __syncthreads();

    const size_t jidx = (size_t)b * (T - 1) + t;

    if (tid < N) {
        float s = smf[tid];
        #pragma unroll
        for (int kk = 0; kk < N; kk++) s -= sXs[kk * MA + tid] * smp[kk];
        g_c[jidx * N + tid] = s;
    }
    {
        float2* gj = (float2*)(g_J + jidx * (N * N));
        for (int i2 = tid; i2 < 512; i2 += 128) {
            int r = i2 >> 4, c = (i2 & 15) * 2;
            gj[i2] = *(const float2*)(sXs + r * MA + c);
        }
    }
    {
        float* gm = g_M + jidx * (N * N);
        #pragma unroll
        for (int s = 0; s < 2; s++) {
            const int id = tid + s * 128;
            const int r0 = (id >> 4) * 2, c0 = (id & 15) * 2;
            float2 f0 = *(const float2*)(sSf + r0 * MA + c0);
            float2 f1 = *(const float2*)(sSf + (r0 + 1) * MA + c0);
            float a00 = f0.x, a01 = f0.y, a10 = f1.x, a11 = f1.y;
            #pragma unroll
            for (int kk = 0; kk < N; kk++) {
                float x0 = sXs[kk * MA + r0], x1 = sXs[kk * MA + r0 + 1];
                float2 g = *(const float2*)(sG + kk * MA + c0);
                a00 -= x0 * g.x;  a01 -= x0 * g.y;
                a10 -= x1 * g.x;  a11 -= x1 * g.y;
            }
            *(float2*)(gm + r0 * 32 + c0) = make_float2(a00, a01);
            *(float2*)(gm + (r0 + 1) * 32 + c0) = make_float2(a10, a11);
        }
    }
}

// =====================================================================
// Kernel 3 (Phase A): compose chunk operators. grid (2, 64) per group.
// =====================================================================
__global__ __launch_bounds__(256) void k_scanA(int k_base)
{
    const int k = k_base + blockIdx.x, b = blockIdx.y;
    const int t_lo = CHS * k;
    const int t_hi = (k == NCH - 1) ? (T - 2) : (CHS * k + CHS - 1);
    const int tid = threadIdx.x;

    __shared__ __align__(16) float sXO[N * MA], sMO[N * MA];
    __shared__ __align__(16) float sXt[2][N * MA], sMt[2][N * MA];
    __shared__ __align__(16) float sW[N * MA], sXN[N * MA];
    __shared__ float scO[N], sct[2][N], scN[N];

    const int r0 = (tid >> 4) * 2, c0 = (tid & 15) * 2;
    const int ra = tid >> 4, ca = (tid & 15) * 2;
    const int rb = ra + 16;

    {
        const size_t base = (size_t)b * (T - 1) + t_hi;
        const float2* gx = (const float2*)(g_J + base * (N * N));
        const float2* gm = (const float2*)(g_M + base * (N * N));
        for (int i2 = tid; i2 < 512; i2 += 256) {
            int r = i2 >> 4, c = (i2 & 15) * 2;
            *(float2*)(sXO + r * MA + c) = gx[i2];
            *(float2*)(sMO + r * MA + c) = gm[i2];
        }
        if (tid < N) scO[tid] = g_c[base * N + tid];
    }

    float2 pX0, pX1, pM0, pM1;
    float pc = 0.f;
    if (t_hi - 1 >= t_lo) {
        const size_t base = (size_t)b * (T - 1) + (t_hi - 1);
        const float2* gx = (const float2*)(g_J + base * (N * N));
        const float2* gm = (const float2*)(g_M + base * (N * N));
        pX0 = gx[tid];  pX1 = gx[tid + 256];
        pM0 = gm[tid];  pM1 = gm[tid + 256];
        if (tid < N) pc = g_c[base * N + tid];
    }
    __syncthreads();

    for (int t = t_hi - 1; t >= t_lo; t--) {
        const int buf = (t_hi - 1 - t) & 1;
        *(float2*)(sXt[buf] + ra * MA + ca) = pX0;
        *(float2*)(sXt[buf] + rb * MA + ca) = pX1;
        *(float2*)(sMt[buf] + ra * MA + ca) = pM0;
        *(float2*)(sMt[buf] + rb * MA + ca) = pM1;
        if (tid < N) sct[buf][tid] = pc;
        if (t > t_lo) {
            const size_t base = (size_t)b * (T - 1) + (t - 1);
            const float2* gx = (const float2*)(g_J + base * (N * N));
            const float2* gm = (const float2*)(g_M + base * (N * N));
            pX0 = gx[tid];  pX1 = gx[tid + 256];
            pM0 = gm[tid];  pM1 = gm[tid + 256];
            if (tid < N) pc = g_c[base * N + tid];
        }
        __syncthreads();

        const float* Xt = sXt[buf];
        const float* Mt = sMt[buf];

        {
            const float2* Mr0 = (const float2*)(sMO + r0 * MA);
            const float2* Mr1 = (const float2*)(sMO + (r0 + 1) * MA);
            const float2* Or0 = (const float2*)(sXO + r0 * MA);
            const float2* Or1 = (const float2*)(sXO + (r0 + 1) * MA);
            float w00 = 0, w01 = 0, w10 = 0, w11 = 0;
            float x00 = 0, x01 = 0, x10 = 0, x11 = 0;
            #pragma unroll
            for (int k2 = 0; k2 < 16; k2++) {
                float2 y0 = *(const float2*)(Xt + (2 * k2) * MA + c0);
                float2 y1 = *(const float2*)(Xt + (2 * k2 + 1) * MA + c0);
                float2 m0 = Mr0[k2], m1 = Mr1[k2];
                float2 o0 = Or0[k2], o1 = Or1[k2];
                w00 += m0.x * y0.x + m0.y * y1.x;  w01 += m0.x * y0.y + m0.y * y1.y;
                w10 += m1.x * y0.x + m1.y * y1.x;  w11 += m1.x * y0.y + m1.y * y1.y;
                x00 += o0.x * y0.x + o0.y * y1.x;  x01 += o0.x * y0.y + o0.y * y1.y;
                x10 += o1.x * y0.x + o1.y * y1.x;  x11 += o1.x * y0.y + o1.y * y1.y;
            }
            *(float2*)(sW + r0 * MA + c0) = make_float2(w00, w01);
            *(float2*)(sW + (r0 + 1) * MA + c0) = make_float2(w10, w11);
            *(float2*)(sXN + r0 * MA + c0) = make_float2(x00, x01);
            *(float2*)(sXN + (r0 + 1) * MA + c0) = make_float2(x10, x11);
        }
        if (tid < N) {
            float s = sct[buf][tid];
            #pragma unroll
            for (int j = 0; j < N; j++) s += Xt[j * MA + tid] * scO[j];
            scN[tid] = s;
        }
        __syncthreads();

        {
            float2 f0 = *(const float2*)(Mt + r0 * MA + c0);
            float2 f1 = *(const float2*)(Mt + (r0 + 1) * MA + c0);
            float a00 = f0.x, a01 = f0.y, a10 = f1.x, a11 = f1.y;
            #pragma unroll
            for (int j = 0; j < N; j++) {
                float2 xj = *(const float2*)(Xt + j * MA + r0);
                float2 wj = *(const float2*)(sW + j * MA + c0);
                a00 += xj.x * wj.x;  a01 += xj.x * wj.y;
                a10 += xj.y * wj.x;  a11 += xj.y * wj.y;
            }
            *(float2*)(sMO + r0 * MA + c0) = make_float2(a00, a01);
            *(float2*)(sMO + (r0 + 1) * MA + c0) = make_float2(a10, a11);
            *(float2*)(sXO + r0 * MA + c0) = *(const float2*)(sXN + r0 * MA + c0);
            *(float2*)(sXO + (r0 + 1) * MA + c0) = *(const float2*)(sXN + (r0 + 1) * MA + c0);
        }
        if (tid < N) scO[tid] = scN[tid];
        __syncthreads();
    }

    {
        const size_t obase = (size_t)b * NCH + k;
        float2* gx = (float2*)(g_OX + obase * (N * N));
        float2* gm = (float2*)(g_OM + obase * (N * N));
        for (int i2 = tid; i2 < 512; i2 += 256) {
            int r = i2 >> 4, c = (i2 & 15) * 2;
            gx[i2] = *(const float2*)(sXO + r * MA + c);
            gm[i2] = *(const float2*)(sMO + r * MA + c);
        }
        if (tid < N) g_Oc[obase * N + tid] = scO[tid];
    }
}

// =====================================================================
// Kernel 4 (Phase B): boundary states per batch. grid 64, 256 thr.
// =====================================================================
__global__ __launch_bounds__(256) void k_scanB(float* __restrict__ out)
{
    const int b = blockIdx.x;
    const int tid = threadIdx.x;

    __shared__ __align__(16) float sS[N * MA], sX[N * MA], sMm[N * MA], sW[N * MA];
    __shared__ float smu[N], smuN[N], sc[N];

    const int r0 = (tid >> 4) * 2, c0 = (tid & 15) * 2;

    {
        const size_t btL = (size_t)b * T + (T - 1);
        const float2* gf = (const float2*)(g_Sigf + (btL << 10));
        float2* ge = (float2*)(g_eS + ((size_t)b * NCH + (NCH - 1)) * (N * N));
        for (int i2 = tid; i2 < 512; i2 += 256) {
            int r = i2 >> 4, c = (i2 & 15) * 2;
            float2 v = gf[i2];
            *(float2*)(sS + r * MA + c) = v;
            ge[i2] = v;
            float* o = out + (btL * N + r) * (N + 1) + 1 + c;
            o[0] = v.x; o[1] = v.y;
        }
        if (tid < N) {
            float v = g_muf[btL * N + tid];
            smu[tid] = v;
            g_emu[((size_t)b * NCH + (NCH - 1)) * N + tid] = v;
            out[(btL * N + tid) * (N + 1)] = v;
        }
    }
    __syncthreads();

    for (int k = NCH - 2; k >= 0; k--) {
        const size_t obase = (size_t)b * NCH + (k + 1);
        {
            const float2* gx = (const float2*)(g_OX + obase * (N * N));
            const float2* gm = (const float2*)(g_OM + obase * (N * N));
            for (int i2 = tid; i2 < 512; i2 += 256) {
                int r = i2 >> 4, c = (i2 & 15) * 2;
                *(float2*)(sX + r * MA + c) = gx[i2];
                *(float2*)(sMm + r * MA + c) = gm[i2];
            }
            if (tid < N) sc[tid] = g_Oc[obase * N + tid];
        }
        __syncthreads();

        {
            const float2* Sr0 = (const float2*)(sS + r0 * MA);
            const float2* Sr1 = (const float2*)(sS + (r0 + 1) * MA);
            float a00 = 0, a01 = 0, a10 = 0, a11 = 0;
            #pragma unroll
            for (int k2 = 0; k2 < 16; k2++) {
                float2 x0 = Sr0[k2], x1 = Sr1[k2];
                float2 y0 = *(const float2*)(sX + (2 * k2) * MA + c0);
                float2 y1 = *(const float2*)(sX + (2 * k2 + 1) * MA + c0);
                a00 += x0.x * y0.x + x0.y * y1.x;  a01 += x0.x * y0.y + x0.y * y1.y;
                a10 += x1.x * y0.x + x1.y * y1.x;  a11 += x1.x * y0.y + x1.y * y1.y;
            }
            *(float2*)(sW + r0 * MA + c0) = make_float2(a00, a01);
            *(float2*)(sW + (r0 + 1) * MA + c0) = make_float2(a10, a11);
        }
        if (tid < N) {
            float s = sc[tid];
            #pragma unroll
            for (int j = 0; j < N; j++) s += sX[j * MA + tid] * smu[j];
            smuN[tid] = s;
        }
        __syncthreads();

        {
            float2 f0 = *(const float2*)(sMm + r0 * MA + c0);
            float2 f1 = *(const float2*)(sMm + (r0 + 1) * MA + c0);
            float a00 = f0.x, a01 = f0.y, a10 = f1.x, a11 = f1.y;
            #pragma unroll
            for (int j = 0; j < N; j++) {
                float2 xj = *(const float2*)(sX + j * MA + r0);
                float2 wj = *(const float2*)(sW + j * MA + c0);
                a00 += xj.x * wj.x;  a01 += xj.x * wj.y;
                a10 += xj.y * wj.x;  a11 += xj.y * wj.y;
            }
            *(float2*)(sS + r0 * MA + c0) = make_float2(a00, a01);
            *(float2*)(sS + (r0 + 1) * MA + c0) = make_float2(a10, a11);
            float* ge = g_eS + ((size_t)b * NCH + k) * (N * N);
            *(float2*)(ge + r0 * 32 + c0) = make_float2(a00, a01);
            *(float2*)(ge + (r0 + 1) * 32 + c0) = make_float2(a10, a11);
        }
        if (tid < N) {
            smu[tid] = smuN[tid];
            g_emu[((size_t)b * NCH + k) * N + tid] = smuN[tid];
        }
        __syncthreads();
    }
}

// =====================================================================
// Kernel 5 (Phase C): per-chunk backward recursion. grid (16, 64), 256 thr.
// =====================================================================
__global__ __launch_bounds__(256) void k_scanC(float* __restrict__ out)
{
    const int k = blockIdx.x, b = blockIdx.y;
    const int t_lo = CHS * k;
    const int t_hi = (k == NCH - 1) ? (T - 2) : (CHS * k + CHS - 1);
    const int tid = threadIdx.x;

    __shared__ __align__(16) float sS[N * MA], sW[N * MA];
    __shared__ __align__(16) float sX[2][N * MA], sMm[2][N * MA];
    __shared__ float smu[N], smuN[N], sc[2][N];

    const int r0 = (tid >> 4) * 2, c0 = (tid & 15) * 2;
    const int ra = tid >> 4, ca = (tid & 15) * 2;
    const int rb = ra + 16;

    {
        const size_t ebase = (size_t)b * NCH + k;
        const float2* ge = (const float2*)(g_eS + ebase * (N * N));
        for (int i2 = tid; i2 < 512; i2 += 256) {
            int r = i2 >> 4, c = (i2 & 15) * 2;
            *(float2*)(sS + r * MA + c) = ge[i2];
        }
        if (tid < N) smu[tid] = g_emu[ebase * N + tid];
    }

    float2 pX0, pX1, pM0, pM1;
    float pc = 0.f;
    {
        const size_t base = (size_t)b * (T - 1) + t_hi;
        const float2* gx = (const float2*)(g_J + base * (N * N));
        const float2* gm = (const float2*)(g_M + base * (N * N));
        pX0 = gx[tid];  pX1 = gx[tid + 256];
        pM0 = gm[tid];  pM1 = gm[tid + 256];
        if (tid < N) pc = g_c[base * N + tid];
    }
    __syncthreads();

    for (int t = t_hi; t >= t_lo; t--) {
        const int buf = (t_hi - t) & 1;
        const size_t bt = (size_t)b * T + t;
        *(float2*)(sX[buf] + ra * MA + ca) = pX0;
        *(float2*)(sX[buf] + rb * MA + ca) = pX1;
        *(float2*)(sMm[buf] + ra * MA + ca) = pM0;
        *(float2*)(sMm[buf] + rb * MA + ca) = pM1;
        if (tid < N) sc[buf][tid] = pc;
        if (t > t_lo) {
            const size_t base = (size_t)b * (T - 1) + (t - 1);
            const float2* gx = (const float2*)(g_J + base * (N * N));
            const float2* gm = (const float2*)(g_M + base * (N * N));
            pX0 = gx[tid];  pX1 = gx[tid + 256];
            pM0 = gm[tid];  pM1 = gm[tid + 256];
            if (tid < N) pc = g_c[base * N + tid];
        }
        __syncthreads();

        const float* Xb = sX[buf];
        const float* Mb = sMm[buf];

        {
            const float2* Sr0 = (const float2*)(sS + r0 * MA);
            const float2* Sr1 = (const float2*)(sS + (r0 + 1) * MA);
            float a00 = 0, a01 = 0, a10 = 0, a11 = 0;
            #pragma unroll
            for (int k2 = 0; k2 < 16; k2++) {
                float2 x0 = Sr0[k2], x1 = Sr1[k2];
                float2 y0 = *(const float2*)(Xb + (2 * k2) * MA + c0);
                float2 y1 = *(const float2*)(Xb + (2 * k2 + 1) * MA + c0);
                a00 += x0.x * y0.x + x0.y * y1.x;  a01 += x0.x * y0.y + x0.y * y1.y;
                a10 += x1.x * y0.x + x1.y * y1.x;  a11 += x1.x * y0.y + x1.y * y1.y;
            }
            *(float2*)(sW + r0 * MA + c0) = make_float2(a00, a01);
            *(float2*)(sW + (r0 + 1) * MA + c0) = make_float2(a10, a11);
        }
        if (tid < N) {
            float s = sc[buf][tid];
            #pragma unroll
            for (int j = 0; j < N; j++) s += Xb[j * MA + tid] * smu[j];
            smuN[tid] = s;
        }
        __syncthreads();

        {
            float2 f0 = *(const float2*)(Mb + r0 * MA + c0);
            float2 f1 = *(const float2*)(Mb + (r0 + 1) * MA + c0);
            float a00 = f0.x, a01 = f0.y, a10 = f1.x, a11 = f1.y;
            #pragma unroll
            for (int j = 0; j < N; j++) {
                float2 xj = *(const float2*)(Xb + j * MA + r0);
                float2 wj = *(const float2*)(sW + j * MA + c0);
                a00 += xj.x * wj.x;  a01 += xj.x * wj.y;
                a10 += xj.y * wj.x;  a11 += xj.y * wj.y;
            }
            *(float2*)(sS + r0 * MA + c0) = make_float2(a00, a01);
            *(float2*)(sS + (r0 + 1) * MA + c0) = make_float2(a10, a11);
            float* o = out + (bt * N + r0) * (N + 1) + 1 + c0;
            o[0] = a00; o[1] = a01;
            o[N + 1] = a10; o[N + 2] = a11;
        }
        if (tid < N) {
            smu[tid] = smuN[tid];
            out[(bt * N + tid) * (N + 1)] = smuN[tid];
        }
        __syncthreads();
    }
}

extern "C" void kernel_launch(void* const* d_in, const int* in_sizes, int n_in,
                              void* d_out, int out_size) {
    (void)in_sizes; (void)n_in; (void)out_size;
    const float* Y   = (const float*)d_in[0];
    const float* U   = (const float*)d_in[1];
    const float* A   = (const float*)d_in[2];
    const float* Bm  = (const float*)d_in[3];
    const float* C   = (const float*)d_in[4];
    const float* mu0 = (const float*)d_in[5];
    const float* S0  = (const float*)d_in[6];
    float* out = (float*)d_out;

    static cudaStream_t s2 = nullptr;
    static cudaEvent_t evF[NSL];
    static cudaEvent_t evJoin;
    if (!s2) {
        cudaStreamCreateWithFlags(&s2, cudaStreamNonBlocking);
        for (int i = 0; i < NSL; i++)
            cudaEventCreateWithFlags(&evF[i], cudaEventDisableTiming);
        cudaEventCreateWithFlags(&evJoin, cudaEventDisableTiming);
    }

    // forward slices on the capture (legacy) stream; backward overlapped on s2
    for (int s = 0; s < NSL; s++) {
        k_fwd<<<BATCH, NTF>>>(Y, U, A, Bm, C, mu0, S0, s * SLT, (s + 1) * SLT);
        cudaEventRecord(evF[s], 0);
        if (s >= 1) {
            // J2 slice s-1 covers t in [ (s-1)*SLT, s*SLT ): needs Sigp up to s*SLT
            cudaStreamWaitEvent(s2, evF[s], 0);
            k_J2<<<dim3(SLT, BATCH), 128, 0, s2>>>(A, (s - 1) * SLT);
            k_scanA<<<dim3(2, BATCH), 256, 0, s2>>>((s - 1) * 2);
        }
    }
    // last J2 slice: t in [ (NSL-1)*SLT, T-1 )  -> 15 blocks
    cudaStreamWaitEvent(s2, evF[NSL - 1], 0);
    k_J2<<<dim3(SLT - 1, BATCH), 128, 0, s2>>>(A, (NSL - 1) * SLT);
    k_scanA<<<dim3(2, BATCH), 256, 0, s2>>>((NSL - 1) * 2);
    k_scanB<<<BATCH, 256, 0, s2>>>(out);
    k_scanC<<<dim3(NCH, BATCH), 256, 0, s2>>>(out);
    cudaEventRecord(evJoin, s2);
    cudaStreamWaitEvent(0, evJoin, 0);
}